// round 12
// baseline (speedup 1.0000x reference)
#include <cuda_runtime.h>
#include <cuda_fp16.h>
#include <cstdint>

#define N_NODES 4096
#define N_EDGES 16384
#define D_OUT   256
#define SPLITK  4

#define NTILES   528
#define NCTA_A   296                           // 148 SMs x 2 CTAs: one wave
// global chunk space: 528 tiles x 256 chunks = 135168; CTA i gets 456+(i<192)
#define GBASE    456L
#define GREM     192L

// ------------------------------------------------------------------
// Scratch (device globals; no allocation allowed)
// ------------------------------------------------------------------
__device__ float  g_s[N_EDGES];
__device__ __half g_Ta[(size_t)N_NODES * N_EDGES];     // fp16(T)
__device__ __half g_Tb[(size_t)N_NODES * N_EDGES];     // fp16(T * s)
__device__ __half g_HWh[(size_t)D_OUT * N_NODES];      // (H_v @ W)^T, fp16, [n][k]
__device__ __half g_Madj[(size_t)N_NODES * N_NODES];   // masked multiplier (fp16)
__device__ __half g_part[(size_t)SPLITK * N_NODES * D_OUT]; // gemm2 split-K partials
__device__ float  g_Cpart[(size_t)NTILES * 2 * 16384]; // SYRK piece partials (SoA)

// ------------------------------------------------------------------
// Helpers
// ------------------------------------------------------------------
__device__ __forceinline__ void cp_async16(void* sptr, const void* gptr) {
    uint32_t saddr = (uint32_t)__cvta_generic_to_shared(sptr);
    asm volatile("cp.async.cg.shared.global [%0], [%1], 16;" :: "r"(saddr), "l"(gptr));
}
__device__ __forceinline__ void cp_commit() {
    asm volatile("cp.async.commit_group;" ::: "memory");
}
template <int NWAIT>
__device__ __forceinline__ void cp_wait() {
    asm volatile("cp.async.wait_group %0;" :: "n"(NWAIT) : "memory");
}
// fp16 m16n8k16, fp32 accumulate
__device__ __forceinline__ void mma_fp16(float& d0, float& d1, float& d2, float& d3,
                                         uint32_t a0, uint32_t a1, uint32_t a2, uint32_t a3,
                                         uint32_t b0, uint32_t b1) {
    asm volatile(
        "mma.sync.aligned.m16n8k16.row.col.f32.f16.f16.f32 "
        "{%0,%1,%2,%3}, {%4,%5,%6,%7}, {%8,%9}, {%0,%1,%2,%3};"
        : "+f"(d0), "+f"(d1), "+f"(d2), "+f"(d3)
        : "r"(a0), "r"(a1), "r"(a2), "r"(a3), "r"(b0), "r"(b1));
}
__device__ __forceinline__ void ldsm_x4(uint32_t& r0, uint32_t& r1, uint32_t& r2, uint32_t& r3,
                                        uint32_t addr) {
    asm volatile("ldmatrix.sync.aligned.m8n8.x4.shared.b16 {%0,%1,%2,%3}, [%4];"
                 : "=r"(r0), "=r"(r1), "=r"(r2), "=r"(r3) : "r"(addr));
}
__device__ __forceinline__ long range_start(long i) {
    return (i <= GREM) ? (GBASE + 1) * i : GBASE * i + GREM;
}

// ------------------------------------------------------------------
// Kernel 1: per-edge scalar  s[e] = edge_features[e,:] . p
// ------------------------------------------------------------------
__global__ void edge_s_kernel(const float* __restrict__ ef, const float* __restrict__ p) {
    int e = blockIdx.x * 256 + threadIdx.x;
    if (e < N_EDGES)
        g_s[e] = ef[e * 3 + 0] * p[0] + ef[e * 3 + 1] * p[1] + ef[e * 3 + 2] * p[2];
}

// ------------------------------------------------------------------
// Kernel 2: Ta = fp16(T), Tb = fp16(T * s)
// ------------------------------------------------------------------
__global__ void scale2_kernel(const float* __restrict__ T) {
    size_t idx = (size_t)blockIdx.x * 256 + threadIdx.x;      // float4 index
    float4 t4 = reinterpret_cast<const float4*>(T)[idx];
    int col4 = (int)(idx & (N_EDGES / 4 - 1));
    float4 s4 = reinterpret_cast<const float4*>(g_s)[col4];
    __half2* A2 = reinterpret_cast<__half2*>(g_Ta);
    __half2* B2 = reinterpret_cast<__half2*>(g_Tb);
    A2[idx * 2]     = __floats2half2_rn(t4.x, t4.y);
    A2[idx * 2 + 1] = __floats2half2_rn(t4.z, t4.w);
    B2[idx * 2]     = __floats2half2_rn(t4.x * s4.x, t4.y * s4.y);
    B2[idx * 2 + 1] = __floats2half2_rn(t4.z * s4.z, t4.w * s4.w);
}

// ------------------------------------------------------------------
// SIMT sgemm: HWt[n][k] = fp16((H_v @ W)[k][n])  (BM=64, 256 CTAs)
// ------------------------------------------------------------------
__global__ __launch_bounds__(256) void sgemm_kernel(
    const float* __restrict__ A, const float* __restrict__ B,
    __half* __restrict__ Ct, int M, int N, int K)
{
    __shared__ float As[16][64];
    __shared__ float Bs[16][64];
    const int tid = threadIdx.x;
    const int m0 = blockIdx.y * 64;
    const int n0 = blockIdx.x * 64;
    const int tm = (tid >> 4) * 4;
    const int tn = (tid & 15) * 4;

    float acc[4][4];
#pragma unroll
    for (int u = 0; u < 4; u++)
#pragma unroll
        for (int w = 0; w < 4; w++) acc[u][w] = 0.f;

    for (int k0 = 0; k0 < K; k0 += 16) {
        {
            int r = tid >> 2;
            int c4 = (tid & 3) * 4;
            float4 av = *reinterpret_cast<const float4*>(&A[(size_t)(m0 + r) * K + k0 + c4]);
            As[c4 + 0][r] = av.x; As[c4 + 1][r] = av.y;
            As[c4 + 2][r] = av.z; As[c4 + 3][r] = av.w;
        }
        {
            int r = tid >> 4;
            int c4 = (tid & 15) * 4;
            *reinterpret_cast<float4*>(&Bs[r][c4]) =
                *reinterpret_cast<const float4*>(&B[(size_t)(k0 + r) * N + n0 + c4]);
        }
        __syncthreads();
#pragma unroll
        for (int k = 0; k < 16; k++) {
            float a[4], b[4];
#pragma unroll
            for (int u = 0; u < 4; u++) a[u] = As[k][tm + u];
            float4 bv = *reinterpret_cast<float4*>(&Bs[k][tn]);
            b[0] = bv.x; b[1] = bv.y; b[2] = bv.z; b[3] = bv.w;
#pragma unroll
            for (int u = 0; u < 4; u++)
#pragma unroll
                for (int w = 0; w < 4; w++) acc[u][w] += a[u] * b[w];
        }
        __syncthreads();
    }
#pragma unroll
    for (int u = 0; u < 4; u++)
#pragma unroll
        for (int w = 0; w < 4; w++)
            Ct[(size_t)(n0 + tn + w) * N_NODES + m0 + tm + u] = __float2half(acc[u][w]);
}

// ------------------------------------------------------------------
// SYRK phase A: balanced chunk-range schedule, ONE wave of 296 CTAs.
// Each CTA covers a contiguous range of the global (tile-major) chunk
// sequence; per tile-piece it accumulates and writes fp32 partials in
// SoA layout (reg-major, coalesced) to g_Cpart[tile][side].
// ------------------------------------------------------------------
#define BKH     64                              // K halves per chunk
#define BKHP    72                              // padded row stride (halves)
#define STAGES  3
#define MAT_HALVES (128 * BKHP)                 // 9216
#define STAGE_HALVES (2 * MAT_HALVES)           // 18432 (36 KB)
#define SYRK_SMEM (STAGES * STAGE_HALVES * 2)   // 110592 B

__global__ __launch_bounds__(256, 2) void syrk_phaseA(void)
{
    extern __shared__ __align__(16) char smemc[];
    __half* smem = reinterpret_cast<__half*>(smemc);
    const int tid = threadIdx.x;
    const int wid = tid >> 5, lane = tid & 31;
    const int wm = (wid & 1) * 64;
    const int wn = (wid >> 1) * 32;

    // ldmatrix per-lane source rows/cols
    const int l7 = lane & 7;
    const int aRow = wm + l7 + 8 * ((lane >> 3) & 1);
    const int aK   = 8 * ((lane >> 4) & 1);
    const int bRow = wn + l7 + 8 * ((lane >> 4) & 1);
    const int bK   = 8 * ((lane >> 3) & 1);
    const uint32_t smem32 = (uint32_t)__cvta_generic_to_shared(smem);
    const uint32_t aOff = (uint32_t)(aRow * BKHP + aK) * 2;
    const uint32_t bOff = (uint32_t)(bRow * BKHP + bK) * 2 + MAT_HALVES * 2;

    const int ci = blockIdx.x;
    long cur = range_start(ci);
    const long end = range_start(ci + 1);

    while (cur < end) {
        const int tile = (int)(cur >> 8);
        const int c0 = (int)(cur & 255);
        const int c1 = (int)((end - cur < (long)(256 - c0)) ? c0 + (end - cur) : 256);

        // decode tile -> (bx, by), column-major lower triangle
        int tt = tile, bx = 0, cnt = 32;
        while (tt >= cnt) { tt -= cnt; bx++; cnt--; }
        const int by = bx + tt;

        const __half* gA = g_Ta + (size_t)by * 128 * N_EDGES;
        const __half* gB = g_Tb + (size_t)bx * 128 * N_EDGES;

        float acc[4][4][4];
#pragma unroll
        for (int mt = 0; mt < 4; mt++)
#pragma unroll
            for (int nt = 0; nt < 4; nt++)
#pragma unroll
                for (int i = 0; i < 4; i++) acc[mt][nt][i] = 0.f;

        auto load_stage = [&](int chunk, int buf) {
            __half* aS = smem + buf * STAGE_HALVES;
            __half* bS = aS + MAT_HALVES;
            const __half* pa = gA + (size_t)chunk * BKH;
            const __half* pb = gB + (size_t)chunk * BKH;
#pragma unroll
            for (int i = 0; i < 4; i++) {
                int v = tid + i * 256;
                int r = v >> 3;
                int c8 = v & 7;
                size_t go = (size_t)r * N_EDGES + c8 * 8;
                cp_async16(aS + r * BKHP + c8 * 8, pa + go);
                cp_async16(bS + r * BKHP + c8 * 8, pb + go);
            }
        };

        if (c0 < c1)     { load_stage(c0, c0 % STAGES); cp_commit(); }
        if (c0 + 1 < c1) { load_stage(c0 + 1, (c0 + 1) % STAGES); cp_commit(); }

        for (int kc = c0; kc < c1; kc++) {
            const int nk = kc + STAGES - 1;
            if (nk < c1) load_stage(nk, nk % STAGES);
            cp_commit();
            cp_wait<STAGES - 2>();
            __syncthreads();

            const uint32_t stageBase = smem32 + (uint32_t)((kc % STAGES) * STAGE_HALVES) * 2;
            const uint32_t aAddr = stageBase + aOff;
            const uint32_t bAddr = stageBase + bOff;

#pragma unroll
            for (int k0 = 0; k0 < BKH; k0 += 16) {
                uint32_t a[4][4];
#pragma unroll
                for (int mt = 0; mt < 4; mt++)
                    ldsm_x4(a[mt][0], a[mt][1], a[mt][2], a[mt][3],
                            aAddr + (uint32_t)(mt * 16 * BKHP + k0) * 2);
                uint32_t b[4][2];
                ldsm_x4(b[0][0], b[0][1], b[1][0], b[1][1],
                        bAddr + (uint32_t)k0 * 2);
                ldsm_x4(b[2][0], b[2][1], b[3][0], b[3][1],
                        bAddr + (uint32_t)(16 * BKHP + k0) * 2);
#pragma unroll
                for (int mt = 0; mt < 4; mt++)
#pragma unroll
                    for (int nt = 0; nt < 4; nt++)
                        mma_fp16(acc[mt][nt][0], acc[mt][nt][1], acc[mt][nt][2], acc[mt][nt][3],
                                 a[mt][0], a[mt][1], a[mt][2], a[mt][3],
                                 b[nt][0], b[nt][1]);
            }
            __syncthreads();
        }
        cp_wait<0>();   // drain before buffers are reused by next piece

        // write fp32 partials, SoA (reg-major): coalesced STG.32
        const int side = (c0 == 0) ? 0 : 1;
        float* P = g_Cpart + ((size_t)tile * 2 + side) * 16384 + tid;
#pragma unroll
        for (int mt = 0; mt < 4; mt++)
#pragma unroll
            for (int nt = 0; nt < 4; nt++)
#pragma unroll
                for (int i = 0; i < 4; i++)
                    P[(size_t)((mt * 16 + nt * 4 + i)) * 256] = acc[mt][nt][i];

        cur += (c1 - c0);
    }
}

// ------------------------------------------------------------------
// SYRK combine: per tile, sum the (1 or 2) fixed partials, apply the
// adj mask, write Madj fp16 (direct lower + mirrored upper).
// ------------------------------------------------------------------
#define COMB_SMEM (128 * 129 * 4)               // 66048 B

__global__ __launch_bounds__(256) void syrk_combine(const float* __restrict__ adj)
{
    extern __shared__ float Cs[];               // 128 x 129
    const int t = blockIdx.x;
    int tt = t, bx = 0, cnt = 32;
    while (tt >= cnt) { tt -= cnt; bx++; cnt--; }
    const int by = bx + tt;

    const long S = (long)t << 8;
    const long ci = (S < (GBASE + 1) * GREM) ? (S / (GBASE + 1)) : ((S - GREM) / GBASE);
    const bool has2 = (range_start(ci + 1) < S + 256);

    const int tid = threadIdx.x;
    const int wid = tid >> 5, lane = tid & 31;
    const int grp = lane >> 2, qid = lane & 3;
    const int wm = (wid & 1) * 64;
    const int wn = (wid >> 1) * 32;

    const float* P0 = g_Cpart + ((size_t)t * 2 + 0) * 16384 + tid;
    const float* P1 = g_Cpart + ((size_t)t * 2 + 1) * 16384 + tid;
#pragma unroll
    for (int mt = 0; mt < 4; mt++)
#pragma unroll
        for (int nt = 0; nt < 4; nt++)
#pragma unroll
            for (int i = 0; i < 4; i++) {
                const int ridx = mt * 16 + nt * 4 + i;
                float v = P0[(size_t)ridx * 256];
                if (has2) v += P1[(size_t)ridx * 256];
                const int r = wm + mt * 16 + grp + ((i >= 2) ? 8 : 0);
                const int c = wn + nt * 8 + qid * 2 + (i & 1);
                Cs[r * 129 + c] = v;
            }
    __syncthreads();

#pragma unroll 4
    for (int step = 0; step < 64; step++) {
        int idx = step * 256 + tid;
        int r = idx >> 7, c = idx & 127;
        size_t gi = (size_t)by * 128 + r;
        size_t gj = (size_t)bx * 128 + c;
        float v = Cs[r * 129 + c];
        float a = adj[gi * N_NODES + gj];
        g_Madj[gi * N_NODES + gj] = __float2half((gi == gj) ? a : v * a);
    }
    if (bx != by) {
#pragma unroll 4
        for (int step = 0; step < 64; step++) {
            int idx = step * 256 + tid;
            int c = idx >> 7, r = idx & 127;   // lanes sweep r -> coalesced
            size_t gi = (size_t)by * 128 + r;
            size_t gj = (size_t)bx * 128 + c;
            float v = Cs[r * 129 + c];
            g_Madj[gj * N_NODES + gi] = __float2half(v * adj[gj * N_NODES + gi]);
        }
    }
}

// ------------------------------------------------------------------
// GEMM2 (fp16 mma + ldmatrix, split-K): part[ks] = Madj[:,slab] @ HWt[:,slab]^T
// ------------------------------------------------------------------
#define G2_KC   (N_NODES / SPLITK)              // 1024
#define G2_NKC  (G2_KC / BKH)                   // 16
#define G2_A_HALVES (128 * BKHP)                // 9216
#define G2_B_HALVES (64 * BKHP)                 // 4608
#define G2_STAGE (G2_A_HALVES + G2_B_HALVES)    // 13824
#define G2_SMEM (STAGES * G2_STAGE * 2)         // 82944 B

__global__ __launch_bounds__(256, 2) void gemm2_fp16(void)
{
    extern __shared__ __align__(16) char smemc[];
    __half* smem = reinterpret_cast<__half*>(smemc);
    const int tid = threadIdx.x;
    const int wid = tid >> 5, lane = tid & 31;
    const int grp = lane >> 2, qid = lane & 3;
    const int wm = (wid & 1) * 64;
    const int wn = (wid >> 1) * 16;
    const int m0 = blockIdx.y * 128;
    const int n0 = blockIdx.x * 64;
    const int kbase = blockIdx.z * G2_KC;

    const __half* gA = g_Madj + (size_t)m0 * N_NODES + kbase;
    const __half* gB = g_HWh + (size_t)n0 * N_NODES + kbase;

    const int l7 = lane & 7;
    const int aRow = wm + l7 + 8 * ((lane >> 3) & 1);
    const int aK   = 8 * ((lane >> 4) & 1);
    const int bRow = wn + l7 + 8 * ((lane >> 4) & 1);
    const int bK   = 8 * ((lane >> 3) & 1);
    const uint32_t smem32 = (uint32_t)__cvta_generic_to_shared(smem);
    const uint32_t aOff = (uint32_t)(aRow * BKHP + aK) * 2;
    const uint32_t bOff = (uint32_t)(bRow * BKHP + bK) * 2 + G2_A_HALVES * 2;

    float acc[4][2][4];
#pragma unroll
    for (int mt = 0; mt < 4; mt++)
#pragma unroll
        for (int nt = 0; nt < 2; nt++)
#pragma unroll
            for (int i = 0; i < 4; i++) acc[mt][nt][i] = 0.f;

    auto load_stage = [&](int chunk, int buf) {
        __half* aS = smem + buf * G2_STAGE;
        __half* bS = aS + G2_A_HALVES;
        const __half* pa = gA + (size_t)chunk * BKH;
        const __half* pb = gB + (size_t)chunk * BKH;
#pragma unroll
        for (int i = 0; i < 6; i++) {
            int v = tid + i * 256;
            int r = v >> 3;
            int c8 = v & 7;
            if (r < 128) {
                cp_async16(aS + r * BKHP + c8 * 8,
                           pa + (size_t)r * N_NODES + c8 * 8);
            } else {
                int rb = r - 128;
                cp_async16(bS + rb * BKHP + c8 * 8,
                           pb + (size_t)rb * N_NODES + c8 * 8);
            }
        }
    };

#pragma unroll
    for (int c = 0; c < STAGES - 1; c++) { load_stage(c, c); cp_commit(); }

    for (int kc = 0; kc < G2_NKC; kc++) {
        const int nk = kc + STAGES - 1;
        if (nk < G2_NKC) load_stage(nk, nk % STAGES);
        cp_commit();
        cp_wait<STAGES - 2>();
        __syncthreads();

        const uint32_t stageBase = smem32 + (uint32_t)((kc % STAGES) * G2_STAGE) * 2;
        const uint32_t aAddr = stageBase + aOff;
        const uint32_t bAddr = stageBase + bOff;

#pragma unroll
        for (int k0 = 0; k0 < BKH; k0 += 16) {
            uint32_t a[4][4];
#pragma unroll
            for (int mt = 0; mt < 4; mt++)
                ldsm_x4(a[mt][0], a[mt][1], a[mt][2], a[mt][3],
                        aAddr + (uint32_t)(mt * 16 * BKHP + k0) * 2);
            uint32_t b[2][2];
            ldsm_x4(b[0][0], b[0][1], b[1][0], b[1][1],
                    bAddr + (uint32_t)k0 * 2);
#pragma unroll
            for (int mt = 0; mt < 4; mt++)
#pragma unroll
                for (int nt = 0; nt < 2; nt++)
                    mma_fp16(acc[mt][nt][0], acc[mt][nt][1], acc[mt][nt][2], acc[mt][nt][3],
                             a[mt][0], a[mt][1], a[mt][2], a[mt][3],
                             b[nt][0], b[nt][1]);
        }
        __syncthreads();
    }

    __half* P = g_part + (size_t)blockIdx.z * N_NODES * D_OUT;
#pragma unroll
    for (int mt = 0; mt < 4; mt++)
#pragma unroll
        for (int nt = 0; nt < 2; nt++) {
            int r = m0 + wm + mt * 16 + grp;
            int c = n0 + wn + nt * 8 + qid * 2;
            P[(size_t)r * D_OUT + c]           = __float2half(acc[mt][nt][0]);
            P[(size_t)r * D_OUT + c + 1]       = __float2half(acc[mt][nt][1]);
            P[(size_t)(r + 8) * D_OUT + c]     = __float2half(acc[mt][nt][2]);
            P[(size_t)(r + 8) * D_OUT + c + 1] = __float2half(acc[mt][nt][3]);
        }
}

// ------------------------------------------------------------------
// Reduce split-K fp16 partials (in fp32) + bias
// ------------------------------------------------------------------
__global__ void reduce_bias_kernel(float* __restrict__ out, const float* __restrict__ bias) {
    size_t idx = (size_t)blockIdx.x * 256 + threadIdx.x;      // 4-element unit
    const __half2* P2 = reinterpret_cast<const __half2*>(g_part);
    const size_t stride2 = (size_t)N_NODES * D_OUT / 2;
    float4 v = make_float4(0.f, 0.f, 0.f, 0.f);
#pragma unroll
    for (int s = 0; s < SPLITK; s++) {
        float2 lo = __half22float2(P2[idx * 2 + s * stride2]);
        float2 hi = __half22float2(P2[idx * 2 + 1 + s * stride2]);
        v.x += lo.x; v.y += lo.y; v.z += hi.x; v.w += hi.y;
    }
    float4 b = reinterpret_cast<const float4*>(bias)[idx & (D_OUT / 4 - 1)];
    v.x += b.x; v.y += b.y; v.z += b.z; v.w += b.w;
    reinterpret_cast<float4*>(out)[idx] = v;
}

// ------------------------------------------------------------------
// Launch
// ------------------------------------------------------------------
extern "C" void kernel_launch(void* const* d_in, const int* in_sizes, int n_in,
                              void* d_out, int out_size) {
    const float* H_v  = (const float*)d_in[0];
    const float* ef   = (const float*)d_in[1];
    const float* adj  = (const float*)d_in[2];
    const float* T    = (const float*)d_in[3];
    const float* W    = (const float*)d_in[4];
    const float* bias = (const float*)d_in[5];
    const float* p    = (const float*)d_in[6];
    float* out = (float*)d_out;

    __half* pHWh = nullptr;
    cudaGetSymbolAddress((void**)&pHWh, g_HWh);

    cudaFuncSetAttribute(syrk_phaseA,
                         cudaFuncAttributeMaxDynamicSharedMemorySize, SYRK_SMEM);
    cudaFuncSetAttribute(syrk_combine,
                         cudaFuncAttributeMaxDynamicSharedMemorySize, COMB_SMEM);
    cudaFuncSetAttribute(gemm2_fp16,
                         cudaFuncAttributeMaxDynamicSharedMemorySize, G2_SMEM);

    // 1. per-edge scalar
    edge_s_kernel<<<N_EDGES / 256, 256>>>(ef, p);
    // 2. Ta = fp16(T), Tb = fp16(T*s)
    scale2_kernel<<<(int)(((size_t)N_NODES * N_EDGES / 4) / 256), 256>>>(T);
    // 3. HWt = fp16((H_v @ W)^T)
    sgemm_kernel<<<dim3(D_OUT / 64, N_NODES / 64), 256>>>(H_v, W, pHWh, N_NODES, D_OUT, 256);
    // 4a. SYRK phase A: balanced single-wave accumulation into partials
    syrk_phaseA<<<NCTA_A, 256, SYRK_SMEM>>>();
    // 4b. combine partials + adj mask -> Madj (fp16)
    syrk_combine<<<NTILES, 256, COMB_SMEM>>>(adj);
    // 5. part = Madj @ HWt^T (split-K fp16 mma, fp16 partials)
    gemm2_fp16<<<dim3(D_OUT / 64, N_NODES / 128, SPLITK), 256, G2_SMEM>>>();
    // 6. out = sum(part) + bias
    reduce_bias_kernel<<<(N_NODES * D_OUT / 4) / 256, 256>>>(out, bias);
}

// round 13
// speedup vs baseline: 1.0447x; 1.0447x over previous
#include <cuda_runtime.h>
#include <cuda_fp16.h>
#include <cstdint>

#define N_NODES 4096
#define N_EDGES 16384
#define D_OUT   256

// ------------------------------------------------------------------
// Scratch (device globals; no allocation allowed)
// ------------------------------------------------------------------
__device__ float  g_s[N_EDGES];
__device__ __half g_Ta[(size_t)N_NODES * N_EDGES];     // fp16(T)
__device__ __half g_Tb[(size_t)N_NODES * N_EDGES];     // fp16(T * s)
__device__ __half g_HWh[(size_t)D_OUT * N_NODES];      // (H_v @ W)^T, fp16, [n][k]
__device__ __half g_Madj[(size_t)N_NODES * N_NODES];   // masked multiplier (fp16)

// ------------------------------------------------------------------
// Helpers
// ------------------------------------------------------------------
__device__ __forceinline__ void cp_async16(void* sptr, const void* gptr) {
    uint32_t saddr = (uint32_t)__cvta_generic_to_shared(sptr);
    asm volatile("cp.async.cg.shared.global [%0], [%1], 16;" :: "r"(saddr), "l"(gptr));
}
__device__ __forceinline__ void cp_commit() {
    asm volatile("cp.async.commit_group;" ::: "memory");
}
template <int NWAIT>
__device__ __forceinline__ void cp_wait() {
    asm volatile("cp.async.wait_group %0;" :: "n"(NWAIT) : "memory");
}
// fp16 m16n8k16, fp32 accumulate
__device__ __forceinline__ void mma_fp16(float& d0, float& d1, float& d2, float& d3,
                                         uint32_t a0, uint32_t a1, uint32_t a2, uint32_t a3,
                                         uint32_t b0, uint32_t b1) {
    asm volatile(
        "mma.sync.aligned.m16n8k16.row.col.f32.f16.f16.f32 "
        "{%0,%1,%2,%3}, {%4,%5,%6,%7}, {%8,%9}, {%0,%1,%2,%3};"
        : "+f"(d0), "+f"(d1), "+f"(d2), "+f"(d3)
        : "r"(a0), "r"(a1), "r"(a2), "r"(a3), "r"(b0), "r"(b1));
}
__device__ __forceinline__ void ldsm_x4(uint32_t& r0, uint32_t& r1, uint32_t& r2, uint32_t& r3,
                                        uint32_t addr) {
    asm volatile("ldmatrix.sync.aligned.m8n8.x4.shared.b16 {%0,%1,%2,%3}, [%4];"
                 : "=r"(r0), "=r"(r1), "=r"(r2), "=r"(r3) : "r"(addr));
}

// ------------------------------------------------------------------
// Kernel 1: per-edge scalar  s[e] = edge_features[e,:] . p
// ------------------------------------------------------------------
__global__ void edge_s_kernel(const float* __restrict__ ef, const float* __restrict__ p) {
    int e = blockIdx.x * 256 + threadIdx.x;
    if (e < N_EDGES)
        g_s[e] = ef[e * 3 + 0] * p[0] + ef[e * 3 + 1] * p[1] + ef[e * 3 + 2] * p[2];
}

// ------------------------------------------------------------------
// Kernel 2: Ta = fp16(T), Tb = fp16(T * s)
// ------------------------------------------------------------------
__global__ void scale2_kernel(const float* __restrict__ T) {
    size_t idx = (size_t)blockIdx.x * 256 + threadIdx.x;      // float4 index
    float4 t4 = reinterpret_cast<const float4*>(T)[idx];
    int col4 = (int)(idx & (N_EDGES / 4 - 1));
    float4 s4 = reinterpret_cast<const float4*>(g_s)[col4];
    __half2* A2 = reinterpret_cast<__half2*>(g_Ta);
    __half2* B2 = reinterpret_cast<__half2*>(g_Tb);
    A2[idx * 2]     = __floats2half2_rn(t4.x, t4.y);
    A2[idx * 2 + 1] = __floats2half2_rn(t4.z, t4.w);
    B2[idx * 2]     = __floats2half2_rn(t4.x * s4.x, t4.y * s4.y);
    B2[idx * 2 + 1] = __floats2half2_rn(t4.z * s4.z, t4.w * s4.w);
}

// ------------------------------------------------------------------
// SIMT sgemm: HWt[n][k] = fp16((H_v @ W)[k][n])  (BM=64, 256 CTAs)
// ------------------------------------------------------------------
__global__ __launch_bounds__(256) void sgemm_kernel(
    const float* __restrict__ A, const float* __restrict__ B,
    __half* __restrict__ Ct, int M, int N, int K)
{
    __shared__ float As[16][64];
    __shared__ float Bs[16][64];
    const int tid = threadIdx.x;
    const int m0 = blockIdx.y * 64;
    const int n0 = blockIdx.x * 64;
    const int tm = (tid >> 4) * 4;
    const int tn = (tid & 15) * 4;

    float acc[4][4];
#pragma unroll
    for (int u = 0; u < 4; u++)
#pragma unroll
        for (int w = 0; w < 4; w++) acc[u][w] = 0.f;

    for (int k0 = 0; k0 < K; k0 += 16) {
        {
            int r = tid >> 2;
            int c4 = (tid & 3) * 4;
            float4 av = *reinterpret_cast<const float4*>(&A[(size_t)(m0 + r) * K + k0 + c4]);
            As[c4 + 0][r] = av.x; As[c4 + 1][r] = av.y;
            As[c4 + 2][r] = av.z; As[c4 + 3][r] = av.w;
        }
        {
            int r = tid >> 4;
            int c4 = (tid & 15) * 4;
            *reinterpret_cast<float4*>(&Bs[r][c4]) =
                *reinterpret_cast<const float4*>(&B[(size_t)(k0 + r) * N + n0 + c4]);
        }
        __syncthreads();
#pragma unroll
        for (int k = 0; k < 16; k++) {
            float a[4], b[4];
#pragma unroll
            for (int u = 0; u < 4; u++) a[u] = As[k][tm + u];
            float4 bv = *reinterpret_cast<float4*>(&Bs[k][tn]);
            b[0] = bv.x; b[1] = bv.y; b[2] = bv.z; b[3] = bv.w;
#pragma unroll
            for (int u = 0; u < 4; u++)
#pragma unroll
                for (int w = 0; w < 4; w++) acc[u][w] += a[u] * b[w];
        }
        __syncthreads();
    }
#pragma unroll
    for (int u = 0; u < 4; u++)
#pragma unroll
        for (int w = 0; w < 4; w++)
            Ct[(size_t)(n0 + tn + w) * N_NODES + m0 + tm + u] = __float2half(acc[u][w]);
}

// ------------------------------------------------------------------
// SYRK via mma.sync fp16 + ldmatrix (R11-proven config):
//   C = Ta @ Tb^T (symmetric). 1D grid, column-major lower triangle.
//   Madj[i,j] = (i==j) ? adj[i,j] : C[i,j]*adj[i,j]; mirror to upper.
// 128x128 tile, BK=64 halves, 3-stage cp.async, 8 warps (2x4),
// warp tile 64x32, 2 CTAs/SM.
// ------------------------------------------------------------------
#define BKH     64                              // K halves per chunk
#define BKHP    72                              // padded row stride (halves)
#define NKCH    (N_EDGES / BKH)                 // 256
#define STAGES  3
#define MAT_HALVES (128 * BKHP)                 // 9216
#define STAGE_HALVES (2 * MAT_HALVES)           // 18432 (36 KB)
#define SYRK_SMEM (STAGES * STAGE_HALVES * 2)   // 110592 B (>= 128*129*4 epilogue)

__global__ __launch_bounds__(256, 2) void syrk_fp16_kernel(const float* __restrict__ adj)
{
    // decode 1D index -> (bx, by), column-major over lower triangle (by >= bx)
    int t = blockIdx.x;
    int bx = 0, cnt = 32;
    while (t >= cnt) { t -= cnt; bx++; cnt--; }
    const int by = bx + t;

    extern __shared__ __align__(16) char smemc[];
    __half* smem = reinterpret_cast<__half*>(smemc);
    const int tid = threadIdx.x;
    const int wid = tid >> 5, lane = tid & 31;
    const int grp = lane >> 2, qid = lane & 3;
    const int wm = (wid & 1) * 64;
    const int wn = (wid >> 1) * 32;

    const __half* gA = g_Ta + (size_t)by * 128 * N_EDGES;
    const __half* gB = g_Tb + (size_t)bx * 128 * N_EDGES;

    // ldmatrix per-lane source rows/cols
    const int l7 = lane & 7;
    const int aRow = wm + l7 + 8 * ((lane >> 3) & 1);
    const int aK   = 8 * ((lane >> 4) & 1);
    const int bRow = wn + l7 + 8 * ((lane >> 4) & 1);
    const int bK   = 8 * ((lane >> 3) & 1);
    const uint32_t smem32 = (uint32_t)__cvta_generic_to_shared(smem);
    const uint32_t aOff = (uint32_t)(aRow * BKHP + aK) * 2;
    const uint32_t bOff = (uint32_t)(bRow * BKHP + bK) * 2 + MAT_HALVES * 2;

    float acc[4][4][4];
#pragma unroll
    for (int mt = 0; mt < 4; mt++)
#pragma unroll
        for (int nt = 0; nt < 4; nt++)
#pragma unroll
            for (int i = 0; i < 4; i++) acc[mt][nt][i] = 0.f;

    auto load_stage = [&](int chunk, int buf) {
        __half* aS = smem + buf * STAGE_HALVES;
        __half* bS = aS + MAT_HALVES;
        const __half* pa = gA + (size_t)chunk * BKH;
        const __half* pb = gB + (size_t)chunk * BKH;
#pragma unroll
        for (int i = 0; i < 4; i++) {
            int v = tid + i * 256;              // 0..1023
            int r = v >> 3;                     // row 0..127
            int c8 = v & 7;                     // which 16B (8 halves) in row
            size_t go = (size_t)r * N_EDGES + c8 * 8;
            cp_async16(aS + r * BKHP + c8 * 8, pa + go);
            cp_async16(bS + r * BKHP + c8 * 8, pb + go);
        }
    };

#pragma unroll
    for (int c = 0; c < STAGES - 1; c++) { load_stage(c, c); cp_commit(); }

    for (int kc = 0; kc < NKCH; kc++) {
        const int nk = kc + STAGES - 1;
        if (nk < NKCH) load_stage(nk, nk % STAGES);
        cp_commit();
        cp_wait<STAGES - 2>();
        __syncthreads();

        const uint32_t stageBase = smem32 + (uint32_t)((kc % STAGES) * STAGE_HALVES) * 2;
        const uint32_t aAddr = stageBase + aOff;
        const uint32_t bAddr = stageBase + bOff;

#pragma unroll
        for (int k0 = 0; k0 < BKH; k0 += 16) {
            uint32_t a[4][4];
#pragma unroll
            for (int mt = 0; mt < 4; mt++)
                ldsm_x4(a[mt][0], a[mt][1], a[mt][2], a[mt][3],
                        aAddr + (uint32_t)(mt * 16 * BKHP + k0) * 2);
            uint32_t b[4][2];
            ldsm_x4(b[0][0], b[0][1], b[1][0], b[1][1],
                    bAddr + (uint32_t)k0 * 2);
            ldsm_x4(b[2][0], b[2][1], b[3][0], b[3][1],
                    bAddr + (uint32_t)(16 * BKHP + k0) * 2);
#pragma unroll
            for (int mt = 0; mt < 4; mt++)
#pragma unroll
                for (int nt = 0; nt < 4; nt++)
                    mma_fp16(acc[mt][nt][0], acc[mt][nt][1], acc[mt][nt][2], acc[mt][nt][3],
                             a[mt][0], a[mt][1], a[mt][2], a[mt][3],
                             b[nt][0], b[nt][1]);
        }
        __syncthreads();
    }

    // ---- epilogue: stage C through smem, coalesced masked fp16 writes ----
    float* Cs = reinterpret_cast<float*>(smemc);          // 128 x 129
#pragma unroll
    for (int mt = 0; mt < 4; mt++)
#pragma unroll
        for (int nt = 0; nt < 4; nt++) {
            int r = wm + mt * 16 + grp;
            int c = wn + nt * 8 + qid * 2;
            Cs[r * 129 + c]           = acc[mt][nt][0];
            Cs[r * 129 + c + 1]       = acc[mt][nt][1];
            Cs[(r + 8) * 129 + c]     = acc[mt][nt][2];
            Cs[(r + 8) * 129 + c + 1] = acc[mt][nt][3];
        }
    __syncthreads();

#pragma unroll 4
    for (int step = 0; step < 64; step++) {
        int idx = step * 256 + tid;
        int r = idx >> 7, c = idx & 127;
        size_t gi = (size_t)by * 128 + r;
        size_t gj = (size_t)bx * 128 + c;
        float v = Cs[r * 129 + c];
        float a = adj[gi * N_NODES + gj];
        g_Madj[gi * N_NODES + gj] = __float2half((gi == gj) ? a : v * a);
    }
    if (bx != by) {
#pragma unroll 4
        for (int step = 0; step < 64; step++) {
            int idx = step * 256 + tid;
            int c = idx >> 7, r = idx & 127;   // lanes sweep r -> coalesced
            size_t gi = (size_t)by * 128 + r;
            size_t gj = (size_t)bx * 128 + c;
            float v = Cs[r * 129 + c];
            g_Madj[gj * N_NODES + gi] = __float2half(v * adj[gj * N_NODES + gi]);
        }
    }
}

// ------------------------------------------------------------------
// GEMM2 fused (fp16 mma + ldmatrix, single pass, K=4096, bias inline):
//   out[m][n] = sum_k Madj[m][k] * HWt[n][k] + bias[n]
// BM=64, BN=64, 8 warps (2x4), warp tile 32x16, BK=64 halves, 3 stages,
// 256 CTAs (one wave, 2/SM). No split-K partials, no reduce kernel.
// ------------------------------------------------------------------
#define F_NKC   (N_NODES / BKH)                 // 64
#define F_A_HALVES (64 * BKHP)                  // 4608
#define F_STAGE (2 * F_A_HALVES)                // 9216 halves (18432 B)
#define F_SMEM (STAGES * F_STAGE * 2)           // 55296 B

__global__ __launch_bounds__(256, 2) void gemm2_fused(
    float* __restrict__ out, const float* __restrict__ bias)
{
    extern __shared__ __align__(16) char smemc[];
    __half* smem = reinterpret_cast<__half*>(smemc);
    const int tid = threadIdx.x;
    const int wid = tid >> 5, lane = tid & 31;
    const int grp = lane >> 2, qid = lane & 3;
    const int wm = (wid & 1) * 32;
    const int wn = (wid >> 1) * 16;
    const int m0 = blockIdx.y * 64;
    const int n0 = blockIdx.x * 64;

    const __half* gA = g_Madj + (size_t)m0 * N_NODES;
    const __half* gB = g_HWh + (size_t)n0 * N_NODES;

    const int l7 = lane & 7;
    const int aRow = wm + l7 + 8 * ((lane >> 3) & 1);
    const int aK   = 8 * ((lane >> 4) & 1);
    const int bRow = wn + l7 + 8 * ((lane >> 4) & 1);
    const int bK   = 8 * ((lane >> 3) & 1);
    const uint32_t smem32 = (uint32_t)__cvta_generic_to_shared(smem);
    const uint32_t aOff = (uint32_t)(aRow * BKHP + aK) * 2;
    const uint32_t bOff = (uint32_t)(bRow * BKHP + bK) * 2 + F_A_HALVES * 2;

    float acc[2][2][4];
#pragma unroll
    for (int mt = 0; mt < 2; mt++)
#pragma unroll
        for (int nt = 0; nt < 2; nt++)
#pragma unroll
            for (int i = 0; i < 4; i++) acc[mt][nt][i] = 0.f;

    auto load_stage = [&](int chunk, int buf) {
        __half* aS = smem + buf * F_STAGE;
        __half* bS = aS + F_A_HALVES;
        const __half* pa = gA + (size_t)chunk * BKH;
        const __half* pb = gB + (size_t)chunk * BKH;
#pragma unroll
        for (int i = 0; i < 4; i++) {
            int v = tid + i * 256;              // 0..1023
            int r = v >> 3;                     // 0..127 (A:0-63, B:64-127)
            int c8 = v & 7;
            if (r < 64) {
                cp_async16(aS + r * BKHP + c8 * 8,
                           pa + (size_t)r * N_NODES + c8 * 8);
            } else {
                int rb = r - 64;
                cp_async16(bS + rb * BKHP + c8 * 8,
                           pb + (size_t)rb * N_NODES + c8 * 8);
            }
        }
    };

#pragma unroll
    for (int c = 0; c < STAGES - 1; c++) { load_stage(c, c); cp_commit(); }

    for (int kc = 0; kc < F_NKC; kc++) {
        const int nk = kc + STAGES - 1;
        if (nk < F_NKC) load_stage(nk, nk % STAGES);
        cp_commit();
        cp_wait<STAGES - 2>();
        __syncthreads();

        const uint32_t stageBase = smem32 + (uint32_t)((kc % STAGES) * F_STAGE) * 2;
        const uint32_t aAddr = stageBase + aOff;
        const uint32_t bAddr = stageBase + bOff;

#pragma unroll
        for (int k0 = 0; k0 < BKH; k0 += 16) {
            uint32_t a[2][4];
#pragma unroll
            for (int mt = 0; mt < 2; mt++)
                ldsm_x4(a[mt][0], a[mt][1], a[mt][2], a[mt][3],
                        aAddr + (uint32_t)(mt * 16 * BKHP + k0) * 2);
            uint32_t b[2][2];
            ldsm_x4(b[0][0], b[0][1], b[1][0], b[1][1],
                    bAddr + (uint32_t)k0 * 2);
#pragma unroll
            for (int mt = 0; mt < 2; mt++)
#pragma unroll
                for (int nt = 0; nt < 2; nt++)
                    mma_fp16(acc[mt][nt][0], acc[mt][nt][1], acc[mt][nt][2], acc[mt][nt][3],
                             a[mt][0], a[mt][1], a[mt][2], a[mt][3],
                             b[nt][0], b[nt][1]);
        }
        __syncthreads();
    }

    // epilogue: + bias, direct fp32 stores to out
#pragma unroll
    for (int mt = 0; mt < 2; mt++)
#pragma unroll
        for (int nt = 0; nt < 2; nt++) {
            int r = m0 + wm + mt * 16 + grp;
            int c = n0 + wn + nt * 8 + qid * 2;
            float b0 = bias[c], b1 = bias[c + 1];
            out[(size_t)r * D_OUT + c]           = acc[mt][nt][0] + b0;
            out[(size_t)r * D_OUT + c + 1]       = acc[mt][nt][1] + b1;
            out[(size_t)(r + 8) * D_OUT + c]     = acc[mt][nt][2] + b0;
            out[(size_t)(r + 8) * D_OUT + c + 1] = acc[mt][nt][3] + b1;
        }
}

// ------------------------------------------------------------------
// Launch
// ------------------------------------------------------------------
extern "C" void kernel_launch(void* const* d_in, const int* in_sizes, int n_in,
                              void* d_out, int out_size) {
    const float* H_v  = (const float*)d_in[0];
    const float* ef   = (const float*)d_in[1];
    const float* adj  = (const float*)d_in[2];
    const float* T    = (const float*)d_in[3];
    const float* W    = (const float*)d_in[4];
    const float* bias = (const float*)d_in[5];
    const float* p    = (const float*)d_in[6];
    float* out = (float*)d_out;

    __half* pHWh = nullptr;
    cudaGetSymbolAddress((void**)&pHWh, g_HWh);

    cudaFuncSetAttribute(syrk_fp16_kernel,
                         cudaFuncAttributeMaxDynamicSharedMemorySize, SYRK_SMEM);
    cudaFuncSetAttribute(gemm2_fused,
                         cudaFuncAttributeMaxDynamicSharedMemorySize, F_SMEM);

    // 1. per-edge scalar
    edge_s_kernel<<<N_EDGES / 256, 256>>>(ef, p);
    // 2. Ta = fp16(T), Tb = fp16(T*s)
    scale2_kernel<<<(int)(((size_t)N_NODES * N_EDGES / 4) / 256), 256>>>(T);
    // 3. HWt = fp16((H_v @ W)^T)
    sgemm_kernel<<<dim3(D_OUT / 64, N_NODES / 64), 256>>>(H_v, W, pHWh, N_NODES, D_OUT, 256);
    // 4. Madj = fp16(mask(Ta @ Tb^T))   [fp16 mma + ldmatrix, symmetric]
    syrk_fp16_kernel<<<528, 256, SYRK_SMEM>>>(adj);
    // 5. out = Madj @ HWt^T + bias (single-pass fp16 mma, fused epilogue)
    gemm2_fused<<<dim3(D_OUT / 64, N_NODES / 64), 256, F_SMEM>>>(out, bias);
}

// round 14
// speedup vs baseline: 1.0947x; 1.0478x over previous
#include <cuda_runtime.h>
#include <cuda_fp16.h>
#include <cstdint>

#define N_NODES 4096
#define N_EDGES 16384
#define D_OUT   256

#define NTILES   528
#define NCTA_A   296                            // 148 SMs x 2 CTAs: one wave
#define GBASE    456L
#define GREM     192L

// ------------------------------------------------------------------
// Scratch (device globals; no allocation allowed)
// ------------------------------------------------------------------
__device__ float  g_s[N_EDGES];
__device__ __half g_Ta[(size_t)N_NODES * N_EDGES];     // fp16(T)
__device__ __half g_Tb[(size_t)N_NODES * N_EDGES];     // fp16(T * s)
__device__ __half g_HWh[(size_t)D_OUT * N_NODES];      // (H_v @ W)^T, fp16, [n][k]
__device__ __half g_Madj[(size_t)N_NODES * N_NODES];   // masked multiplier (fp16)
__device__ float  g_Cpart[(size_t)NTILES * 16384];     // head-piece partials (SoA)
__device__ int    g_flag[NTILES];                      // head-piece ready flags

// ------------------------------------------------------------------
// Helpers
// ------------------------------------------------------------------
__device__ __forceinline__ void cp_async16(void* sptr, const void* gptr) {
    uint32_t saddr = (uint32_t)__cvta_generic_to_shared(sptr);
    asm volatile("cp.async.cg.shared.global [%0], [%1], 16;" :: "r"(saddr), "l"(gptr));
}
__device__ __forceinline__ void cp_commit() {
    asm volatile("cp.async.commit_group;" ::: "memory");
}
template <int NWAIT>
__device__ __forceinline__ void cp_wait() {
    asm volatile("cp.async.wait_group %0;" :: "n"(NWAIT) : "memory");
}
// fp16 m16n8k16, fp32 accumulate
__device__ __forceinline__ void mma_fp16(float& d0, float& d1, float& d2, float& d3,
                                         uint32_t a0, uint32_t a1, uint32_t a2, uint32_t a3,
                                         uint32_t b0, uint32_t b1) {
    asm volatile(
        "mma.sync.aligned.m16n8k16.row.col.f32.f16.f16.f32 "
        "{%0,%1,%2,%3}, {%4,%5,%6,%7}, {%8,%9}, {%0,%1,%2,%3};"
        : "+f"(d0), "+f"(d1), "+f"(d2), "+f"(d3)
        : "r"(a0), "r"(a1), "r"(a2), "r"(a3), "r"(b0), "r"(b1));
}
__device__ __forceinline__ void ldsm_x4(uint32_t& r0, uint32_t& r1, uint32_t& r2, uint32_t& r3,
                                        uint32_t addr) {
    asm volatile("ldmatrix.sync.aligned.m8n8.x4.shared.b16 {%0,%1,%2,%3}, [%4];"
                 : "=r"(r0), "=r"(r1), "=r"(r2), "=r"(r3) : "r"(addr));
}
__device__ __forceinline__ long range_start(long i) {
    return (i <= GREM) ? (GBASE + 1) * i : GBASE * i + GREM;
}

// ------------------------------------------------------------------
// Kernel 1: per-edge scalar + zero the SYRK flags (fresh per replay)
// ------------------------------------------------------------------
__global__ void edge_s_kernel(const float* __restrict__ ef, const float* __restrict__ p) {
    int e = blockIdx.x * 256 + threadIdx.x;
    if (e < NTILES) g_flag[e] = 0;
    if (e < N_EDGES)
        g_s[e] = ef[e * 3 + 0] * p[0] + ef[e * 3 + 1] * p[1] + ef[e * 3 + 2] * p[2];
}

// ------------------------------------------------------------------
// Kernel 2: Ta = fp16(T), Tb = fp16(T * s)
// ------------------------------------------------------------------
__global__ void scale2_kernel(const float* __restrict__ T) {
    size_t idx = (size_t)blockIdx.x * 256 + threadIdx.x;      // float4 index
    float4 t4 = reinterpret_cast<const float4*>(T)[idx];
    int col4 = (int)(idx & (N_EDGES / 4 - 1));
    float4 s4 = reinterpret_cast<const float4*>(g_s)[col4];
    __half2* A2 = reinterpret_cast<__half2*>(g_Ta);
    __half2* B2 = reinterpret_cast<__half2*>(g_Tb);
    A2[idx * 2]     = __floats2half2_rn(t4.x, t4.y);
    A2[idx * 2 + 1] = __floats2half2_rn(t4.z, t4.w);
    B2[idx * 2]     = __floats2half2_rn(t4.x * s4.x, t4.y * s4.y);
    B2[idx * 2 + 1] = __floats2half2_rn(t4.z * s4.z, t4.w * s4.w);
}

// ------------------------------------------------------------------
// SIMT sgemm: HWt[n][k] = fp16((H_v @ W)[k][n])  (BM=64, 256 CTAs)
// ------------------------------------------------------------------
__global__ __launch_bounds__(256) void sgemm_kernel(
    const float* __restrict__ A, const float* __restrict__ B,
    __half* __restrict__ Ct, int M, int N, int K)
{
    __shared__ float As[16][64];
    __shared__ float Bs[16][64];
    const int tid = threadIdx.x;
    const int m0 = blockIdx.y * 64;
    const int n0 = blockIdx.x * 64;
    const int tm = (tid >> 4) * 4;
    const int tn = (tid & 15) * 4;

    float acc[4][4];
#pragma unroll
    for (int u = 0; u < 4; u++)
#pragma unroll
        for (int w = 0; w < 4; w++) acc[u][w] = 0.f;

    for (int k0 = 0; k0 < K; k0 += 16) {
        {
            int r = tid >> 2;
            int c4 = (tid & 3) * 4;
            float4 av = *reinterpret_cast<const float4*>(&A[(size_t)(m0 + r) * K + k0 + c4]);
            As[c4 + 0][r] = av.x; As[c4 + 1][r] = av.y;
            As[c4 + 2][r] = av.z; As[c4 + 3][r] = av.w;
        }
        {
            int r = tid >> 4;
            int c4 = (tid & 15) * 4;
            *reinterpret_cast<float4*>(&Bs[r][c4]) =
                *reinterpret_cast<const float4*>(&B[(size_t)(k0 + r) * N + n0 + c4]);
        }
        __syncthreads();
#pragma unroll
        for (int k = 0; k < 16; k++) {
            float a[4], b[4];
#pragma unroll
            for (int u = 0; u < 4; u++) a[u] = As[k][tm + u];
            float4 bv = *reinterpret_cast<float4*>(&Bs[k][tn]);
            b[0] = bv.x; b[1] = bv.y; b[2] = bv.z; b[3] = bv.w;
#pragma unroll
            for (int u = 0; u < 4; u++)
#pragma unroll
                for (int w = 0; w < 4; w++) acc[u][w] += a[u] * b[w];
        }
        __syncthreads();
    }
#pragma unroll
    for (int u = 0; u < 4; u++)
#pragma unroll
        for (int w = 0; w < 4; w++)
            Ct[(size_t)(n0 + tn + w) * N_NODES + m0 + tm + u] = __float2half(acc[u][w]);
}

// ------------------------------------------------------------------
// SYRK, balanced one-wave schedule with in-kernel combine:
// 296 CTAs; each covers a contiguous range of the 135168 global chunks.
// Full tiles -> inline masked epilogue. Head fragment (tile start) ->
// partial + release-flag, issued FIRST. Tail fragment -> processed LAST:
// spin-acquire predecessor's flag, add partial, epilogue. Deterministic.
// ------------------------------------------------------------------
#define BKH     64
#define BKHP    72
#define STAGES  3
#define MAT_HALVES (128 * BKHP)                 // 9216
#define STAGE_HALVES (2 * MAT_HALVES)           // 18432 (36 KB)
#define SYRK_SMEM (STAGES * STAGE_HALVES * 2)   // 110592 B (>= 128*129*4 epilogue)

__global__ __launch_bounds__(256, 2) void syrk_sched(const float* __restrict__ adj)
{
    extern __shared__ __align__(16) char smemc[];
    __half* smem = reinterpret_cast<__half*>(smemc);
    const int tid = threadIdx.x;
    const int wid = tid >> 5, lane = tid & 31;
    const int grp = lane >> 2, qid = lane & 3;
    const int wm = (wid & 1) * 64;
    const int wn = (wid >> 1) * 32;

    const int l7 = lane & 7;
    const int aRow = wm + l7 + 8 * ((lane >> 3) & 1);
    const int aK   = 8 * ((lane >> 4) & 1);
    const int bRow = wn + l7 + 8 * ((lane >> 4) & 1);
    const int bK   = 8 * ((lane >> 3) & 1);
    const uint32_t smem32 = (uint32_t)__cvta_generic_to_shared(smem);
    const uint32_t aOff = (uint32_t)(aRow * BKHP + aK) * 2;
    const uint32_t bOff = (uint32_t)(bRow * BKHP + bK) * 2 + MAT_HALVES * 2;

    float acc[4][4][4];
    const __half* gA = nullptr;
    const __half* gB = nullptr;

    auto load_stage = [&](int chunk, int buf) {
        __half* aS = smem + buf * STAGE_HALVES;
        __half* bS = aS + MAT_HALVES;
        const __half* pa = gA + (size_t)chunk * BKH;
        const __half* pb = gB + (size_t)chunk * BKH;
#pragma unroll
        for (int i = 0; i < 4; i++) {
            int v = tid + i * 256;
            int r = v >> 3;
            int c8 = v & 7;
            size_t go = (size_t)r * N_EDGES + c8 * 8;
            cp_async16(aS + r * BKHP + c8 * 8, pa + go);
            cp_async16(bS + r * BKHP + c8 * 8, pb + go);
        }
    };

    // MMA over chunks [c0, c1) of one tile; returns (bx, by) via out-params.
    auto mma_piece = [&](int tile, int c0, int c1, int& bxo, int& byo) {
        int tt = tile, bx = 0, cnt = 32;
        while (tt >= cnt) { tt -= cnt; bx++; cnt--; }
        const int by = bx + tt;
        bxo = bx; byo = by;
        gA = g_Ta + (size_t)by * 128 * N_EDGES;
        gB = g_Tb + (size_t)bx * 128 * N_EDGES;

#pragma unroll
        for (int mt = 0; mt < 4; mt++)
#pragma unroll
            for (int nt = 0; nt < 4; nt++)
#pragma unroll
                for (int i = 0; i < 4; i++) acc[mt][nt][i] = 0.f;

        if (c0 < c1)     { load_stage(c0, c0 % STAGES); cp_commit(); }
        if (c0 + 1 < c1) { load_stage(c0 + 1, (c0 + 1) % STAGES); cp_commit(); }

        for (int kc = c0; kc < c1; kc++) {
            const int nk = kc + STAGES - 1;
            if (nk < c1) load_stage(nk, nk % STAGES);
            cp_commit();
            cp_wait<STAGES - 2>();
            __syncthreads();

            const uint32_t stageBase = smem32 + (uint32_t)((kc % STAGES) * STAGE_HALVES) * 2;
            const uint32_t aAddr = stageBase + aOff;
            const uint32_t bAddr = stageBase + bOff;

#pragma unroll
            for (int k0 = 0; k0 < BKH; k0 += 16) {
                uint32_t a[4][4];
#pragma unroll
                for (int mt = 0; mt < 4; mt++)
                    ldsm_x4(a[mt][0], a[mt][1], a[mt][2], a[mt][3],
                            aAddr + (uint32_t)(mt * 16 * BKHP + k0) * 2);
                uint32_t b[4][2];
                ldsm_x4(b[0][0], b[0][1], b[1][0], b[1][1],
                        bAddr + (uint32_t)k0 * 2);
                ldsm_x4(b[2][0], b[2][1], b[3][0], b[3][1],
                        bAddr + (uint32_t)(16 * BKHP + k0) * 2);
#pragma unroll
                for (int mt = 0; mt < 4; mt++)
#pragma unroll
                    for (int nt = 0; nt < 4; nt++)
                        mma_fp16(acc[mt][nt][0], acc[mt][nt][1], acc[mt][nt][2], acc[mt][nt][3],
                                 a[mt][0], a[mt][1], a[mt][2], a[mt][3],
                                 b[nt][0], b[nt][1]);
            }
            __syncthreads();
        }
        cp_wait<0>();
        __syncthreads();
    };

    // masked epilogue for tile (by, bx) from acc
    auto epilogue = [&](int by, int bx) {
        float* Cs = reinterpret_cast<float*>(smemc);          // 128 x 129
#pragma unroll
        for (int mt = 0; mt < 4; mt++)
#pragma unroll
            for (int nt = 0; nt < 4; nt++) {
                int r = wm + mt * 16 + grp;
                int c = wn + nt * 8 + qid * 2;
                Cs[r * 129 + c]           = acc[mt][nt][0];
                Cs[r * 129 + c + 1]       = acc[mt][nt][1];
                Cs[(r + 8) * 129 + c]     = acc[mt][nt][2];
                Cs[(r + 8) * 129 + c + 1] = acc[mt][nt][3];
            }
        __syncthreads();
#pragma unroll 4
        for (int step = 0; step < 64; step++) {
            int idx = step * 256 + tid;
            int r = idx >> 7, c = idx & 127;
            size_t gi = (size_t)by * 128 + r;
            size_t gj = (size_t)bx * 128 + c;
            float v = Cs[r * 129 + c];
            float a = adj[gi * N_NODES + gj];
            g_Madj[gi * N_NODES + gj] = __float2half((gi == gj) ? a : v * a);
        }
        if (bx != by) {
#pragma unroll 4
            for (int step = 0; step < 64; step++) {
                int idx = step * 256 + tid;
                int c = idx >> 7, r = idx & 127;   // lanes sweep r -> coalesced
                size_t gi = (size_t)by * 128 + r;
                size_t gj = (size_t)bx * 128 + c;
                float v = Cs[r * 129 + c];
                g_Madj[gj * N_NODES + gi] = __float2half(v * adj[gj * N_NODES + gi]);
            }
        }
        __syncthreads();   // protect Cs before next piece's loads
    };

    // ---- decode this CTA's range into (tail | fulls | head) ----
    long s = range_start(blockIdx.x);
    long e = range_start(blockIdx.x + 1);
    int tailTile = -1, tailC0 = 0, headTile = -1, headC1 = 0;
    if (s & 255) { tailTile = (int)(s >> 8); tailC0 = (int)(s & 255); s = (s + 255) & ~255L; }
    if (e & 255) { headTile = (int)(e >> 8); headC1 = (int)(e & 255); e &= ~255L; }

    int bx, by;

    // 1) head fragment FIRST: publish partial asap for the successor
    if (headTile >= 0) {
        mma_piece(headTile, 0, headC1, bx, by);
        float* P = g_Cpart + (size_t)headTile * 16384 + tid;
#pragma unroll
        for (int mt = 0; mt < 4; mt++)
#pragma unroll
            for (int nt = 0; nt < 4; nt++)
#pragma unroll
                for (int i = 0; i < 4; i++)
                    P[(size_t)(mt * 16 + nt * 4 + i) * 256] = acc[mt][nt][i];
        __threadfence();
        __syncthreads();
        if (tid == 0)
            asm volatile("st.global.release.gpu.b32 [%0], %1;"
                         :: "l"(g_flag + headTile), "r"(1) : "memory");
    }

    // 2) full tiles
    for (int t = (int)(s >> 8); t < (int)(e >> 8); t++) {
        mma_piece(t, 0, 256, bx, by);
        epilogue(by, bx);
    }

    // 3) tail fragment LAST: combine with predecessor's head partial
    if (tailTile >= 0) {
        mma_piece(tailTile, tailC0, 256, bx, by);
        if (tid == 0) {
            int v;
            do {
                asm volatile("ld.global.acquire.gpu.b32 %0, [%1];"
                             : "=r"(v) : "l"(g_flag + tailTile) : "memory");
                if (!v) __nanosleep(64);
            } while (!v);
        }
        __syncthreads();
        const float* P = g_Cpart + (size_t)tailTile * 16384 + tid;
#pragma unroll
        for (int mt = 0; mt < 4; mt++)
#pragma unroll
            for (int nt = 0; nt < 4; nt++)
#pragma unroll
                for (int i = 0; i < 4; i++)
                    acc[mt][nt][i] += P[(size_t)(mt * 16 + nt * 4 + i) * 256];
        epilogue(by, bx);
    }
}

// ------------------------------------------------------------------
// GEMM2 fused (fp16 mma + ldmatrix, single pass, K=4096, bias inline):
//   out[m][n] = sum_k Madj[m][k] * HWt[n][k] + bias[n]
// BM=64, BN=128, 8 warps (2x4), warp tile 32x32, BK=64 halves, 3 stages,
// grid (2, 64) = 128 CTAs.
// ------------------------------------------------------------------
#define H_NKC   (N_NODES / BKH)                 // 64
#define H_A_HALVES (64 * BKHP)                  // 4608
#define H_B_HALVES (128 * BKHP)                 // 9216
#define H_STAGE (H_A_HALVES + H_B_HALVES)       // 13824 halves
#define H_SMEM (STAGES * H_STAGE * 2)           // 82944 B

__global__ __launch_bounds__(256, 2) void gemm2_fused(
    float* __restrict__ out, const float* __restrict__ bias)
{
    extern __shared__ __align__(16) char smemc[];
    __half* smem = reinterpret_cast<__half*>(smemc);
    const int tid = threadIdx.x;
    const int wid = tid >> 5, lane = tid & 31;
    const int grp = lane >> 2, qid = lane & 3;
    const int wm = (wid & 1) * 32;
    const int wn = (wid >> 1) * 32;
    const int m0 = blockIdx.y * 64;
    const int n0 = blockIdx.x * 128;

    const __half* gA = g_Madj + (size_t)m0 * N_NODES;
    const __half* gB = g_HWh + (size_t)n0 * N_NODES;

    const int l7 = lane & 7;
    const int aRow = wm + l7 + 8 * ((lane >> 3) & 1);
    const int aK   = 8 * ((lane >> 4) & 1);
    const int bRow = wn + l7 + 8 * ((lane >> 4) & 1);
    const int bK   = 8 * ((lane >> 3) & 1);
    const uint32_t smem32 = (uint32_t)__cvta_generic_to_shared(smem);
    const uint32_t aOff = (uint32_t)(aRow * BKHP + aK) * 2;
    const uint32_t bOff = (uint32_t)(bRow * BKHP + bK) * 2 + H_A_HALVES * 2;

    float acc[2][4][4];
#pragma unroll
    for (int mt = 0; mt < 2; mt++)
#pragma unroll
        for (int nt = 0; nt < 4; nt++)
#pragma unroll
            for (int i = 0; i < 4; i++) acc[mt][nt][i] = 0.f;

    auto load_stage = [&](int chunk, int buf) {
        __half* aS = smem + buf * H_STAGE;
        __half* bS = aS + H_A_HALVES;
        const __half* pa = gA + (size_t)chunk * BKH;
        const __half* pb = gB + (size_t)chunk * BKH;
#pragma unroll
        for (int i = 0; i < 6; i++) {
            int v = tid + i * 256;              // 0..1535
            int r = v >> 3;                     // 0..191 (A:0-63, B:64-191)
            int c8 = v & 7;
            if (r < 64) {
                cp_async16(aS + r * BKHP + c8 * 8,
                           pa + (size_t)r * N_NODES + c8 * 8);
            } else {
                int rb = r - 64;
                cp_async16(bS + rb * BKHP + c8 * 8,
                           pb + (size_t)rb * N_NODES + c8 * 8);
            }
        }
    };

#pragma unroll
    for (int c = 0; c < STAGES - 1; c++) { load_stage(c, c); cp_commit(); }

    for (int kc = 0; kc < H_NKC; kc++) {
        const int nk = kc + STAGES - 1;
        if (nk < H_NKC) load_stage(nk, nk % STAGES);
        cp_commit();
        cp_wait<STAGES - 2>();
        __syncthreads();

        const uint32_t stageBase = smem32 + (uint32_t)((kc % STAGES) * H_STAGE) * 2;
        const uint32_t aAddr = stageBase + aOff;
        const uint32_t bAddr = stageBase + bOff;

#pragma unroll
        for (int k0 = 0; k0 < BKH; k0 += 16) {
            uint32_t a[2][4];
#pragma unroll
            for (int mt = 0; mt < 2; mt++)
                ldsm_x4(a[mt][0], a[mt][1], a[mt][2], a[mt][3],
                        aAddr + (uint32_t)(mt * 16 * BKHP + k0) * 2);
            uint32_t b[4][2];
#pragma unroll
            for (int np = 0; np < 2; np++)
                ldsm_x4(b[2 * np][0], b[2 * np][1], b[2 * np + 1][0], b[2 * np + 1][1],
                        bAddr + (uint32_t)(np * 16 * BKHP + k0) * 2);
#pragma unroll
            for (int mt = 0; mt < 2; mt++)
#pragma unroll
                for (int nt = 0; nt < 4; nt++)
                    mma_fp16(acc[mt][nt][0], acc[mt][nt][1], acc[mt][nt][2], acc[mt][nt][3],
                             a[mt][0], a[mt][1], a[mt][2], a[mt][3],
                             b[nt][0], b[nt][1]);
        }
        __syncthreads();
    }

    // epilogue: + bias, direct fp32 stores
#pragma unroll
    for (int mt = 0; mt < 2; mt++)
#pragma unroll
        for (int nt = 0; nt < 4; nt++) {
            int r = m0 + wm + mt * 16 + grp;
            int c = n0 + wn + nt * 8 + qid * 2;
            float b0 = bias[c], b1 = bias[c + 1];
            out[(size_t)r * D_OUT + c]           = acc[mt][nt][0] + b0;
            out[(size_t)r * D_OUT + c + 1]       = acc[mt][nt][1] + b1;
            out[(size_t)(r + 8) * D_OUT + c]     = acc[mt][nt][2] + b0;
            out[(size_t)(r + 8) * D_OUT + c + 1] = acc[mt][nt][3] + b1;
        }
}

// ------------------------------------------------------------------
// Launch
// ------------------------------------------------------------------
extern "C" void kernel_launch(void* const* d_in, const int* in_sizes, int n_in,
                              void* d_out, int out_size) {
    const float* H_v  = (const float*)d_in[0];
    const float* ef   = (const float*)d_in[1];
    const float* adj  = (const float*)d_in[2];
    const float* T    = (const float*)d_in[3];
    const float* W    = (const float*)d_in[4];
    const float* bias = (const float*)d_in[5];
    const float* p    = (const float*)d_in[6];
    float* out = (float*)d_out;

    __half* pHWh = nullptr;
    cudaGetSymbolAddress((void**)&pHWh, g_HWh);

    cudaFuncSetAttribute(syrk_sched,
                         cudaFuncAttributeMaxDynamicSharedMemorySize, SYRK_SMEM);
    cudaFuncSetAttribute(gemm2_fused,
                         cudaFuncAttributeMaxDynamicSharedMemorySize, H_SMEM);

    // 1. per-edge scalar + flag reset
    edge_s_kernel<<<N_EDGES / 256, 256>>>(ef, p);
    // 2. Ta = fp16(T), Tb = fp16(T*s)
    scale2_kernel<<<(int)(((size_t)N_NODES * N_EDGES / 4) / 256), 256>>>(T);
    // 3. HWt = fp16((H_v @ W)^T)
    sgemm_kernel<<<dim3(D_OUT / 64, N_NODES / 64), 256>>>(H_v, W, pHWh, N_NODES, D_OUT, 256);
    // 4. Madj: balanced one-wave SYRK with in-kernel combine
    syrk_sched<<<NCTA_A, 256, SYRK_SMEM>>>(adj);
    // 5. out = Madj @ HWt^T + bias (single pass, BN=128)
    gemm2_fused<<<dim3(D_OUT / 128, N_NODES / 64), 256, H_SMEM>>>(out, bias);
}

// round 15
// speedup vs baseline: 1.1181x; 1.0214x over previous
#include <cuda_runtime.h>
#include <cuda_fp16.h>
#include <cstdint>

#define N_NODES 4096
#define N_EDGES 16384
#define D_OUT   256

#define NTILES   528
#define NCTA_A   296                            // 148 SMs x 2 CTAs: one wave
#define GBASE    456L
#define GREM     192L

// ------------------------------------------------------------------
// Scratch (device globals; no allocation allowed)
// ------------------------------------------------------------------
__device__ float  g_s[N_EDGES];
__device__ __half g_Ta[(size_t)N_NODES * N_EDGES];     // fp16(T)
__device__ __half g_Tb[(size_t)N_NODES * N_EDGES];     // fp16(T * s)
__device__ __half g_HWh[(size_t)D_OUT * N_NODES];      // (H_v @ W)^T, fp16, [n][k]
__device__ __half g_Madj[(size_t)N_NODES * N_NODES];   // masked multiplier (fp16)
__device__ float  g_Cpart[(size_t)NTILES * 16384];     // head-piece partials (SoA)
__device__ int    g_flag[NTILES];                      // head-piece ready flags

// ------------------------------------------------------------------
// Helpers
// ------------------------------------------------------------------
__device__ __forceinline__ void cp_async16(void* sptr, const void* gptr) {
    uint32_t saddr = (uint32_t)__cvta_generic_to_shared(sptr);
    asm volatile("cp.async.cg.shared.global [%0], [%1], 16;" :: "r"(saddr), "l"(gptr));
}
__device__ __forceinline__ void cp_commit() {
    asm volatile("cp.async.commit_group;" ::: "memory");
}
template <int NWAIT>
__device__ __forceinline__ void cp_wait() {
    asm volatile("cp.async.wait_group %0;" :: "n"(NWAIT) : "memory");
}
// fp16 m16n8k16, fp32 accumulate
__device__ __forceinline__ void mma_fp16(float& d0, float& d1, float& d2, float& d3,
                                         uint32_t a0, uint32_t a1, uint32_t a2, uint32_t a3,
                                         uint32_t b0, uint32_t b1) {
    asm volatile(
        "mma.sync.aligned.m16n8k16.row.col.f32.f16.f16.f32 "
        "{%0,%1,%2,%3}, {%4,%5,%6,%7}, {%8,%9}, {%0,%1,%2,%3};"
        : "+f"(d0), "+f"(d1), "+f"(d2), "+f"(d3)
        : "r"(a0), "r"(a1), "r"(a2), "r"(a3), "r"(b0), "r"(b1));
}
__device__ __forceinline__ void ldsm_x4(uint32_t& r0, uint32_t& r1, uint32_t& r2, uint32_t& r3,
                                        uint32_t addr) {
    asm volatile("ldmatrix.sync.aligned.m8n8.x4.shared.b16 {%0,%1,%2,%3}, [%4];"
                 : "=r"(r0), "=r"(r1), "=r"(r2), "=r"(r3) : "r"(addr));
}
__device__ __forceinline__ long range_start(long i) {
    return (i <= GREM) ? (GBASE + 1) * i : GBASE * i + GREM;
}

// ------------------------------------------------------------------
// Kernel 1: per-edge scalar + zero the SYRK flags (fresh per replay)
// ------------------------------------------------------------------
__global__ void edge_s_kernel(const float* __restrict__ ef, const float* __restrict__ p) {
    int e = blockIdx.x * 256 + threadIdx.x;
    if (e < NTILES) g_flag[e] = 0;
    if (e < N_EDGES)
        g_s[e] = ef[e * 3 + 0] * p[0] + ef[e * 3 + 1] * p[1] + ef[e * 3 + 2] * p[2];
}

// ------------------------------------------------------------------
// Kernel 2: Ta = fp16(T), Tb = fp16(T * s)
// ------------------------------------------------------------------
__global__ void scale2_kernel(const float* __restrict__ T) {
    size_t idx = (size_t)blockIdx.x * 256 + threadIdx.x;      // float4 index
    float4 t4 = reinterpret_cast<const float4*>(T)[idx];
    int col4 = (int)(idx & (N_EDGES / 4 - 1));
    float4 s4 = reinterpret_cast<const float4*>(g_s)[col4];
    __half2* A2 = reinterpret_cast<__half2*>(g_Ta);
    __half2* B2 = reinterpret_cast<__half2*>(g_Tb);
    A2[idx * 2]     = __floats2half2_rn(t4.x, t4.y);
    A2[idx * 2 + 1] = __floats2half2_rn(t4.z, t4.w);
    B2[idx * 2]     = __floats2half2_rn(t4.x * s4.x, t4.y * s4.y);
    B2[idx * 2 + 1] = __floats2half2_rn(t4.z * s4.z, t4.w * s4.w);
}

// ------------------------------------------------------------------
// SIMT sgemm: HWt[n][k] = fp16((H_v @ W)[k][n])  (BM=64, 256 CTAs)
// ------------------------------------------------------------------
__global__ __launch_bounds__(256) void sgemm_kernel(
    const float* __restrict__ A, const float* __restrict__ B,
    __half* __restrict__ Ct, int M, int N, int K)
{
    __shared__ float As[16][64];
    __shared__ float Bs[16][64];
    const int tid = threadIdx.x;
    const int m0 = blockIdx.y * 64;
    const int n0 = blockIdx.x * 64;
    const int tm = (tid >> 4) * 4;
    const int tn = (tid & 15) * 4;

    float acc[4][4];
#pragma unroll
    for (int u = 0; u < 4; u++)
#pragma unroll
        for (int w = 0; w < 4; w++) acc[u][w] = 0.f;

    for (int k0 = 0; k0 < K; k0 += 16) {
        {
            int r = tid >> 2;
            int c4 = (tid & 3) * 4;
            float4 av = *reinterpret_cast<const float4*>(&A[(size_t)(m0 + r) * K + k0 + c4]);
            As[c4 + 0][r] = av.x; As[c4 + 1][r] = av.y;
            As[c4 + 2][r] = av.z; As[c4 + 3][r] = av.w;
        }
        {
            int r = tid >> 4;
            int c4 = (tid & 15) * 4;
            *reinterpret_cast<float4*>(&Bs[r][c4]) =
                *reinterpret_cast<const float4*>(&B[(size_t)(k0 + r) * N + n0 + c4]);
        }
        __syncthreads();
#pragma unroll
        for (int k = 0; k < 16; k++) {
            float a[4], b[4];
#pragma unroll
            for (int u = 0; u < 4; u++) a[u] = As[k][tm + u];
            float4 bv = *reinterpret_cast<float4*>(&Bs[k][tn]);
            b[0] = bv.x; b[1] = bv.y; b[2] = bv.z; b[3] = bv.w;
#pragma unroll
            for (int u = 0; u < 4; u++)
#pragma unroll
                for (int w = 0; w < 4; w++) acc[u][w] += a[u] * b[w];
        }
        __syncthreads();
    }
#pragma unroll
    for (int u = 0; u < 4; u++)
#pragma unroll
        for (int w = 0; w < 4; w++)
            Ct[(size_t)(n0 + tn + w) * N_NODES + m0 + tm + u] = __float2half(acc[u][w]);
}

// ------------------------------------------------------------------
// SYRK, balanced one-wave schedule with in-kernel combine (R14-proven):
// 296 CTAs; each covers a contiguous range of the 135168 global chunks.
// Full tiles -> inline masked epilogue. Head fragment -> partial +
// release-flag, issued FIRST. Tail fragment -> LAST: spin-acquire
// predecessor's flag, add partial, epilogue. Deterministic.
// ------------------------------------------------------------------
#define BKH     64
#define BKHP    72
#define STAGES  3
#define MAT_HALVES (128 * BKHP)                 // 9216
#define STAGE_HALVES (2 * MAT_HALVES)           // 18432 (36 KB)
#define SYRK_SMEM (STAGES * STAGE_HALVES * 2)   // 110592 B (>= 128*129*4 epilogue)

__global__ __launch_bounds__(256, 2) void syrk_sched(const float* __restrict__ adj)
{
    extern __shared__ __align__(16) char smemc[];
    __half* smem = reinterpret_cast<__half*>(smemc);
    const int tid = threadIdx.x;
    const int wid = tid >> 5, lane = tid & 31;
    const int grp = lane >> 2, qid = lane & 3;
    const int wm = (wid & 1) * 64;
    const int wn = (wid >> 1) * 32;

    const int l7 = lane & 7;
    const int aRow = wm + l7 + 8 * ((lane >> 3) & 1);
    const int aK   = 8 * ((lane >> 4) & 1);
    const int bRow = wn + l7 + 8 * ((lane >> 4) & 1);
    const int bK   = 8 * ((lane >> 3) & 1);
    const uint32_t smem32 = (uint32_t)__cvta_generic_to_shared(smem);
    const uint32_t aOff = (uint32_t)(aRow * BKHP + aK) * 2;
    const uint32_t bOff = (uint32_t)(bRow * BKHP + bK) * 2 + MAT_HALVES * 2;

    float acc[4][4][4];
    const __half* gA = nullptr;
    const __half* gB = nullptr;

    auto load_stage = [&](int chunk, int buf) {
        __half* aS = smem + buf * STAGE_HALVES;
        __half* bS = aS + MAT_HALVES;
        const __half* pa = gA + (size_t)chunk * BKH;
        const __half* pb = gB + (size_t)chunk * BKH;
#pragma unroll
        for (int i = 0; i < 4; i++) {
            int v = tid + i * 256;
            int r = v >> 3;
            int c8 = v & 7;
            size_t go = (size_t)r * N_EDGES + c8 * 8;
            cp_async16(aS + r * BKHP + c8 * 8, pa + go);
            cp_async16(bS + r * BKHP + c8 * 8, pb + go);
        }
    };

    auto mma_piece = [&](int tile, int c0, int c1, int& bxo, int& byo) {
        int tt = tile, bx = 0, cnt = 32;
        while (tt >= cnt) { tt -= cnt; bx++; cnt--; }
        const int by = bx + tt;
        bxo = bx; byo = by;
        gA = g_Ta + (size_t)by * 128 * N_EDGES;
        gB = g_Tb + (size_t)bx * 128 * N_EDGES;

#pragma unroll
        for (int mt = 0; mt < 4; mt++)
#pragma unroll
            for (int nt = 0; nt < 4; nt++)
#pragma unroll
                for (int i = 0; i < 4; i++) acc[mt][nt][i] = 0.f;

        if (c0 < c1)     { load_stage(c0, c0 % STAGES); cp_commit(); }
        if (c0 + 1 < c1) { load_stage(c0 + 1, (c0 + 1) % STAGES); cp_commit(); }

        for (int kc = c0; kc < c1; kc++) {
            const int nk = kc + STAGES - 1;
            if (nk < c1) load_stage(nk, nk % STAGES);
            cp_commit();
            cp_wait<STAGES - 2>();
            __syncthreads();

            const uint32_t stageBase = smem32 + (uint32_t)((kc % STAGES) * STAGE_HALVES) * 2;
            const uint32_t aAddr = stageBase + aOff;
            const uint32_t bAddr = stageBase + bOff;

#pragma unroll
            for (int k0 = 0; k0 < BKH; k0 += 16) {
                uint32_t a[4][4];
#pragma unroll
                for (int mt = 0; mt < 4; mt++)
                    ldsm_x4(a[mt][0], a[mt][1], a[mt][2], a[mt][3],
                            aAddr + (uint32_t)(mt * 16 * BKHP + k0) * 2);
                uint32_t b[4][2];
                ldsm_x4(b[0][0], b[0][1], b[1][0], b[1][1],
                        bAddr + (uint32_t)k0 * 2);
                ldsm_x4(b[2][0], b[2][1], b[3][0], b[3][1],
                        bAddr + (uint32_t)(16 * BKHP + k0) * 2);
#pragma unroll
                for (int mt = 0; mt < 4; mt++)
#pragma unroll
                    for (int nt = 0; nt < 4; nt++)
                        mma_fp16(acc[mt][nt][0], acc[mt][nt][1], acc[mt][nt][2], acc[mt][nt][3],
                                 a[mt][0], a[mt][1], a[mt][2], a[mt][3],
                                 b[nt][0], b[nt][1]);
            }
            __syncthreads();
        }
        cp_wait<0>();
        __syncthreads();
    };

    auto epilogue = [&](int by, int bx) {
        float* Cs = reinterpret_cast<float*>(smemc);          // 128 x 129
#pragma unroll
        for (int mt = 0; mt < 4; mt++)
#pragma unroll
            for (int nt = 0; nt < 4; nt++) {
                int r = wm + mt * 16 + grp;
                int c = wn + nt * 8 + qid * 2;
                Cs[r * 129 + c]           = acc[mt][nt][0];
                Cs[r * 129 + c + 1]       = acc[mt][nt][1];
                Cs[(r + 8) * 129 + c]     = acc[mt][nt][2];
                Cs[(r + 8) * 129 + c + 1] = acc[mt][nt][3];
            }
        __syncthreads();
#pragma unroll 4
        for (int step = 0; step < 64; step++) {
            int idx = step * 256 + tid;
            int r = idx >> 7, c = idx & 127;
            size_t gi = (size_t)by * 128 + r;
            size_t gj = (size_t)bx * 128 + c;
            float v = Cs[r * 129 + c];
            float a = adj[gi * N_NODES + gj];
            g_Madj[gi * N_NODES + gj] = __float2half((gi == gj) ? a : v * a);
        }
        if (bx != by) {
#pragma unroll 4
            for (int step = 0; step < 64; step++) {
                int idx = step * 256 + tid;
                int c = idx >> 7, r = idx & 127;   // lanes sweep r -> coalesced
                size_t gi = (size_t)by * 128 + r;
                size_t gj = (size_t)bx * 128 + c;
                float v = Cs[r * 129 + c];
                g_Madj[gj * N_NODES + gi] = __float2half(v * adj[gj * N_NODES + gi]);
            }
        }
        __syncthreads();   // protect Cs before next piece's loads
    };

    long s = range_start(blockIdx.x);
    long e = range_start(blockIdx.x + 1);
    int tailTile = -1, tailC0 = 0, headTile = -1, headC1 = 0;
    if (s & 255) { tailTile = (int)(s >> 8); tailC0 = (int)(s & 255); s = (s + 255) & ~255L; }
    if (e & 255) { headTile = (int)(e >> 8); headC1 = (int)(e & 255); e &= ~255L; }

    int bx, by;

    if (headTile >= 0) {
        mma_piece(headTile, 0, headC1, bx, by);
        float* P = g_Cpart + (size_t)headTile * 16384 + tid;
#pragma unroll
        for (int mt = 0; mt < 4; mt++)
#pragma unroll
            for (int nt = 0; nt < 4; nt++)
#pragma unroll
                for (int i = 0; i < 4; i++)
                    P[(size_t)(mt * 16 + nt * 4 + i) * 256] = acc[mt][nt][i];
        __threadfence();
        __syncthreads();
        if (tid == 0)
            asm volatile("st.global.release.gpu.b32 [%0], %1;"
                         :: "l"(g_flag + headTile), "r"(1) : "memory");
    }

    for (int t = (int)(s >> 8); t < (int)(e >> 8); t++) {
        mma_piece(t, 0, 256, bx, by);
        epilogue(by, bx);
    }

    if (tailTile >= 0) {
        mma_piece(tailTile, tailC0, 256, bx, by);
        if (tid == 0) {
            int v;
            do {
                asm volatile("ld.global.acquire.gpu.b32 %0, [%1];"
                             : "=r"(v) : "l"(g_flag + tailTile) : "memory");
                if (!v) __nanosleep(64);
            } while (!v);
        }
        __syncthreads();
        const float* P = g_Cpart + (size_t)tailTile * 16384 + tid;
#pragma unroll
        for (int mt = 0; mt < 4; mt++)
#pragma unroll
            for (int nt = 0; nt < 4; nt++)
#pragma unroll
                for (int i = 0; i < 4; i++)
                    acc[mt][nt][i] += P[(size_t)(mt * 16 + nt * 4 + i) * 256];
        epilogue(by, bx);
    }
}

// ------------------------------------------------------------------
// GEMM2 fused (fp16 mma + ldmatrix, single pass, K=4096, bias inline):
// BM=64, BN=128, 8 warps (2x4), warp tile 32x32, grid (2, 64).
// ------------------------------------------------------------------
#define H_NKC   (N_NODES / BKH)                 // 64
#define H_A_HALVES (64 * BKHP)                  // 4608
#define H_B_HALVES (128 * BKHP)                 // 9216
#define H_STAGE (H_A_HALVES + H_B_HALVES)       // 13824 halves
#define H_SMEM (STAGES * H_STAGE * 2)           // 82944 B

__global__ __launch_bounds__(256, 2) void gemm2_fused(
    float* __restrict__ out, const float* __restrict__ bias)
{
    extern __shared__ __align__(16) char smemc[];
    __half* smem = reinterpret_cast<__half*>(smemc);
    const int tid = threadIdx.x;
    const int wid = tid >> 5, lane = tid & 31;
    const int grp = lane >> 2, qid = lane & 3;
    const int wm = (wid & 1) * 32;
    const int wn = (wid >> 1) * 32;
    const int m0 = blockIdx.y * 64;
    const int n0 = blockIdx.x * 128;

    const __half* gA = g_Madj + (size_t)m0 * N_NODES;
    const __half* gB = g_HWh + (size_t)n0 * N_NODES;

    const int l7 = lane & 7;
    const int aRow = wm + l7 + 8 * ((lane >> 3) & 1);
    const int aK   = 8 * ((lane >> 4) & 1);
    const int bRow = wn + l7 + 8 * ((lane >> 4) & 1);
    const int bK   = 8 * ((lane >> 3) & 1);
    const uint32_t smem32 = (uint32_t)__cvta_generic_to_shared(smem);
    const uint32_t aOff = (uint32_t)(aRow * BKHP + aK) * 2;
    const uint32_t bOff = (uint32_t)(bRow * BKHP + bK) * 2 + H_A_HALVES * 2;

    float acc[2][4][4];
#pragma unroll
    for (int mt = 0; mt < 2; mt++)
#pragma unroll
        for (int nt = 0; nt < 4; nt++)
#pragma unroll
            for (int i = 0; i < 4; i++) acc[mt][nt][i] = 0.f;

    auto load_stage = [&](int chunk, int buf) {
        __half* aS = smem + buf * H_STAGE;
        __half* bS = aS + H_A_HALVES;
        const __half* pa = gA + (size_t)chunk * BKH;
        const __half* pb = gB + (size_t)chunk * BKH;
#pragma unroll
        for (int i = 0; i < 6; i++) {
            int v = tid + i * 256;              // 0..1535
            int r = v >> 3;                     // 0..191 (A:0-63, B:64-191)
            int c8 = v & 7;
            if (r < 64) {
                cp_async16(aS + r * BKHP + c8 * 8,
                           pa + (size_t)r * N_NODES + c8 * 8);
            } else {
                int rb = r - 64;
                cp_async16(bS + rb * BKHP + c8 * 8,
                           pb + (size_t)rb * N_NODES + c8 * 8);
            }
        }
    };

#pragma unroll
    for (int c = 0; c < STAGES - 1; c++) { load_stage(c, c); cp_commit(); }

    for (int kc = 0; kc < H_NKC; kc++) {
        const int nk = kc + STAGES - 1;
        if (nk < H_NKC) load_stage(nk, nk % STAGES);
        cp_commit();
        cp_wait<STAGES - 2>();
        __syncthreads();

        const uint32_t stageBase = smem32 + (uint32_t)((kc % STAGES) * H_STAGE) * 2;
        const uint32_t aAddr = stageBase + aOff;
        const uint32_t bAddr = stageBase + bOff;

#pragma unroll
        for (int k0 = 0; k0 < BKH; k0 += 16) {
            uint32_t a[2][4];
#pragma unroll
            for (int mt = 0; mt < 2; mt++)
                ldsm_x4(a[mt][0], a[mt][1], a[mt][2], a[mt][3],
                        aAddr + (uint32_t)(mt * 16 * BKHP + k0) * 2);
            uint32_t b[4][2];
#pragma unroll
            for (int np = 0; np < 2; np++)
                ldsm_x4(b[2 * np][0], b[2 * np][1], b[2 * np + 1][0], b[2 * np + 1][1],
                        bAddr + (uint32_t)(np * 16 * BKHP + k0) * 2);
#pragma unroll
            for (int mt = 0; mt < 2; mt++)
#pragma unroll
                for (int nt = 0; nt < 4; nt++)
                    mma_fp16(acc[mt][nt][0], acc[mt][nt][1], acc[mt][nt][2], acc[mt][nt][3],
                             a[mt][0], a[mt][1], a[mt][2], a[mt][3],
                             b[nt][0], b[nt][1]);
        }
        __syncthreads();
    }

#pragma unroll
    for (int mt = 0; mt < 2; mt++)
#pragma unroll
        for (int nt = 0; nt < 4; nt++) {
            int r = m0 + wm + mt * 16 + grp;
            int c = n0 + wn + nt * 8 + qid * 2;
            float b0 = bias[c], b1 = bias[c + 1];
            out[(size_t)r * D_OUT + c]           = acc[mt][nt][0] + b0;
            out[(size_t)r * D_OUT + c + 1]       = acc[mt][nt][1] + b1;
            out[(size_t)(r + 8) * D_OUT + c]     = acc[mt][nt][2] + b0;
            out[(size_t)(r + 8) * D_OUT + c + 1] = acc[mt][nt][3] + b1;
        }
}

// ------------------------------------------------------------------
// Launch: fork sgemm (independent of edge_s/scale2/SYRK) onto a side
// stream so it overlaps the SYRK critical path; join before gemm2.
// Stream/event creation happens only on real kernel_launch calls
// (correctness + capture), not on graph replays.
// ------------------------------------------------------------------
extern "C" void kernel_launch(void* const* d_in, const int* in_sizes, int n_in,
                              void* d_out, int out_size) {
    const float* H_v  = (const float*)d_in[0];
    const float* ef   = (const float*)d_in[1];
    const float* adj  = (const float*)d_in[2];
    const float* T    = (const float*)d_in[3];
    const float* W    = (const float*)d_in[4];
    const float* bias = (const float*)d_in[5];
    const float* p    = (const float*)d_in[6];
    float* out = (float*)d_out;

    __half* pHWh = nullptr;
    cudaGetSymbolAddress((void**)&pHWh, g_HWh);

    cudaFuncSetAttribute(syrk_sched,
                         cudaFuncAttributeMaxDynamicSharedMemorySize, SYRK_SMEM);
    cudaFuncSetAttribute(gemm2_fused,
                         cudaFuncAttributeMaxDynamicSharedMemorySize, H_SMEM);

    cudaStream_t s2 = nullptr;
    cudaEvent_t eFork = nullptr, eJoin = nullptr;
    bool forked = (cudaStreamCreateWithFlags(&s2, cudaStreamNonBlocking) == cudaSuccess)
               && (cudaEventCreateWithFlags(&eFork, cudaEventDisableTiming) == cudaSuccess)
               && (cudaEventCreateWithFlags(&eJoin, cudaEventDisableTiming) == cudaSuccess);

    // 1. per-edge scalar + flag reset (critical path)
    edge_s_kernel<<<N_EDGES / 256, 256>>>(ef, p);

    if (forked) {
        // fork: sgemm depends only on H_v/W -> run on side stream
        cudaEventRecord(eFork, 0);
        cudaStreamWaitEvent(s2, eFork, 0);
        sgemm_kernel<<<dim3(D_OUT / 64, N_NODES / 64), 256, 0, s2>>>(
            H_v, W, pHWh, N_NODES, D_OUT, 256);
        cudaEventRecord(eJoin, s2);
    } else {
        sgemm_kernel<<<dim3(D_OUT / 64, N_NODES / 64), 256>>>(
            H_v, W, pHWh, N_NODES, D_OUT, 256);
    }

    // 2. Ta = fp16(T), Tb = fp16(T*s)
    scale2_kernel<<<(int)(((size_t)N_NODES * N_EDGES / 4) / 256), 256>>>(T);
    // 3. Madj: balanced one-wave SYRK with in-kernel combine
    syrk_sched<<<NCTA_A, 256, SYRK_SMEM>>>(adj);

    if (forked) cudaStreamWaitEvent(0, eJoin, 0);   // join before gemm2

    // 4. out = Madj @ HWt^T + bias (single pass, BN=128)
    gemm2_fused<<<dim3(D_OUT / 128, N_NODES / 64), 256, H_SMEM>>>(out, bias);
}

// round 16
// speedup vs baseline: 1.1252x; 1.0063x over previous
#include <cuda_runtime.h>
#include <cuda_fp16.h>
#include <cstdint>

#define N_NODES 4096
#define N_EDGES 16384
#define D_OUT   256

#define NTILES   528
#define NCTA_A   296                            // 148 SMs x 2 CTAs: one wave
#define GBASE    456L
#define GREM     192L

// ------------------------------------------------------------------
// Scratch (device globals; no allocation allowed)
// ------------------------------------------------------------------
__device__ __half g_sh[N_EDGES];                       // fp16(s)
__device__ __half g_Ta[(size_t)N_NODES * N_EDGES];     // fp16(T)
__device__ __half g_Tb[(size_t)N_NODES * N_EDGES];     // fp16(T) * fp16(s)
__device__ __half g_HWh[(size_t)D_OUT * N_NODES];      // (H_v @ W)^T, fp16, [n][k]
__device__ __half g_Madj[(size_t)N_NODES * N_NODES];   // masked multiplier (fp16)
__device__ float  g_Cpart[(size_t)NTILES * 16384];     // head-piece partials (SoA)
__device__ int    g_flag[NTILES];                      // head-piece ready flags

// ------------------------------------------------------------------
// Helpers
// ------------------------------------------------------------------
__device__ __forceinline__ void cp_async16(void* sptr, const void* gptr) {
    uint32_t saddr = (uint32_t)__cvta_generic_to_shared(sptr);
    asm volatile("cp.async.cg.shared.global [%0], [%1], 16;" :: "r"(saddr), "l"(gptr));
}
__device__ __forceinline__ void cp_commit() {
    asm volatile("cp.async.commit_group;" ::: "memory");
}
template <int NWAIT>
__device__ __forceinline__ void cp_wait() {
    asm volatile("cp.async.wait_group %0;" :: "n"(NWAIT) : "memory");
}
// fp16 m16n8k16, fp32 accumulate
__device__ __forceinline__ void mma_fp16(float& d0, float& d1, float& d2, float& d3,
                                         uint32_t a0, uint32_t a1, uint32_t a2, uint32_t a3,
                                         uint32_t b0, uint32_t b1) {
    asm volatile(
        "mma.sync.aligned.m16n8k16.row.col.f32.f16.f16.f32 "
        "{%0,%1,%2,%3}, {%4,%5,%6,%7}, {%8,%9}, {%0,%1,%2,%3};"
        : "+f"(d0), "+f"(d1), "+f"(d2), "+f"(d3)
        : "r"(a0), "r"(a1), "r"(a2), "r"(a3), "r"(b0), "r"(b1));
}
__device__ __forceinline__ void ldsm_x4(uint32_t& r0, uint32_t& r1, uint32_t& r2, uint32_t& r3,
                                        uint32_t addr) {
    asm volatile("ldmatrix.sync.aligned.m8n8.x4.shared.b16 {%0,%1,%2,%3}, [%4];"
                 : "=r"(r0), "=r"(r1), "=r"(r2), "=r"(r3) : "r"(addr));
}
__device__ __forceinline__ long range_start(long i) {
    return (i <= GREM) ? (GBASE + 1) * i : GBASE * i + GREM;
}

// ------------------------------------------------------------------
// Kernel 1: per-edge scalar (fp16) + zero SYRK flags (fresh per replay)
// ------------------------------------------------------------------
__global__ void edge_s_kernel(const float* __restrict__ ef, const float* __restrict__ p) {
    int e = blockIdx.x * 256 + threadIdx.x;
    if (e < NTILES) g_flag[e] = 0;
    if (e < N_EDGES)
        g_sh[e] = __float2half(ef[e * 3 + 0] * p[0] + ef[e * 3 + 1] * p[1]
                               + ef[e * 3 + 2] * p[2]);
}

// ------------------------------------------------------------------
// Kernel 2: Ta = fp16(T), Tb = Ta (x) fp16(s)  — 8 floats/thread,
// HMUL2 for the scaled side, 16B stores. Issue-lean (~1.6 instr/elem).
// ------------------------------------------------------------------
__global__ void scale2_kernel(const float* __restrict__ T) {
    size_t idx = (size_t)blockIdx.x * 256 + threadIdx.x;      // 8-float unit
    const float4* T4 = reinterpret_cast<const float4*>(T);
    float4 x = T4[idx * 2], y = T4[idx * 2 + 1];

    __half2 a[4];
    a[0] = __floats2half2_rn(x.x, x.y);
    a[1] = __floats2half2_rn(x.z, x.w);
    a[2] = __floats2half2_rn(y.x, y.y);
    a[3] = __floats2half2_rn(y.z, y.w);

    int col8 = (int)(idx & (N_EDGES / 8 - 1));
    float4 sraw = reinterpret_cast<const float4*>(g_sh)[col8];   // 8 halves
    const __half2* s2 = reinterpret_cast<const __half2*>(&sraw);

    __half2 b[4];
#pragma unroll
    for (int i = 0; i < 4; i++) b[i] = __hmul2(a[i], s2[i]);

    reinterpret_cast<float4*>(g_Ta)[idx] = *reinterpret_cast<float4*>(a);
    reinterpret_cast<float4*>(g_Tb)[idx] = *reinterpret_cast<float4*>(b);
}

// ------------------------------------------------------------------
// SIMT sgemm: HWt[n][k] = fp16((H_v @ W)[k][n])  (BM=64, 256 CTAs)
// ------------------------------------------------------------------
__global__ __launch_bounds__(256) void sgemm_kernel(
    const float* __restrict__ A, const float* __restrict__ B,
    __half* __restrict__ Ct, int M, int N, int K)
{
    __shared__ float As[16][64];
    __shared__ float Bs[16][64];
    const int tid = threadIdx.x;
    const int m0 = blockIdx.y * 64;
    const int n0 = blockIdx.x * 64;
    const int tm = (tid >> 4) * 4;
    const int tn = (tid & 15) * 4;

    float acc[4][4];
#pragma unroll
    for (int u = 0; u < 4; u++)
#pragma unroll
        for (int w = 0; w < 4; w++) acc[u][w] = 0.f;

    for (int k0 = 0; k0 < K; k0 += 16) {
        {
            int r = tid >> 2;
            int c4 = (tid & 3) * 4;
            float4 av = *reinterpret_cast<const float4*>(&A[(size_t)(m0 + r) * K + k0 + c4]);
            As[c4 + 0][r] = av.x; As[c4 + 1][r] = av.y;
            As[c4 + 2][r] = av.z; As[c4 + 3][r] = av.w;
        }
        {
            int r = tid >> 4;
            int c4 = (tid & 15) * 4;
            *reinterpret_cast<float4*>(&Bs[r][c4]) =
                *reinterpret_cast<const float4*>(&B[(size_t)(k0 + r) * N + n0 + c4]);
        }
        __syncthreads();
#pragma unroll
        for (int k = 0; k < 16; k++) {
            float a[4], b[4];
#pragma unroll
            for (int u = 0; u < 4; u++) a[u] = As[k][tm + u];
            float4 bv = *reinterpret_cast<float4*>(&Bs[k][tn]);
            b[0] = bv.x; b[1] = bv.y; b[2] = bv.z; b[3] = bv.w;
#pragma unroll
            for (int u = 0; u < 4; u++)
#pragma unroll
                for (int w = 0; w < 4; w++) acc[u][w] += a[u] * b[w];
        }
        __syncthreads();
    }
#pragma unroll
    for (int u = 0; u < 4; u++)
#pragma unroll
        for (int w = 0; w < 4; w++)
            Ct[(size_t)(n0 + tn + w) * N_NODES + m0 + tm + u] = __float2half(acc[u][w]);
}

// ------------------------------------------------------------------
// SYRK, balanced one-wave schedule with in-kernel combine (R14-proven):
// 296 CTAs; each covers a contiguous range of the 135168 global chunks.
// Full tiles -> inline masked epilogue. Head fragment -> partial +
// release-flag, issued FIRST. Tail fragment -> LAST: spin-acquire
// predecessor's flag, add partial, epilogue. Deterministic.
// ------------------------------------------------------------------
#define BKH     64
#define BKHP    72
#define STAGES  3
#define MAT_HALVES (128 * BKHP)                 // 9216
#define STAGE_HALVES (2 * MAT_HALVES)           // 18432 (36 KB)
#define SYRK_SMEM (STAGES * STAGE_HALVES * 2)   // 110592 B (>= 128*129*4 epilogue)

__global__ __launch_bounds__(256, 2) void syrk_sched(const float* __restrict__ adj)
{
    extern __shared__ __align__(16) char smemc[];
    __half* smem = reinterpret_cast<__half*>(smemc);
    const int tid = threadIdx.x;
    const int wid = tid >> 5, lane = tid & 31;
    const int grp = lane >> 2, qid = lane & 3;
    const int wm = (wid & 1) * 64;
    const int wn = (wid >> 1) * 32;

    const int l7 = lane & 7;
    const int aRow = wm + l7 + 8 * ((lane >> 3) & 1);
    const int aK   = 8 * ((lane >> 4) & 1);
    const int bRow = wn + l7 + 8 * ((lane >> 4) & 1);
    const int bK   = 8 * ((lane >> 3) & 1);
    const uint32_t smem32 = (uint32_t)__cvta_generic_to_shared(smem);
    const uint32_t aOff = (uint32_t)(aRow * BKHP + aK) * 2;
    const uint32_t bOff = (uint32_t)(bRow * BKHP + bK) * 2 + MAT_HALVES * 2;

    float acc[4][4][4];
    const __half* gA = nullptr;
    const __half* gB = nullptr;

    auto load_stage = [&](int chunk, int buf) {
        __half* aS = smem + buf * STAGE_HALVES;
        __half* bS = aS + MAT_HALVES;
        const __half* pa = gA + (size_t)chunk * BKH;
        const __half* pb = gB + (size_t)chunk * BKH;
#pragma unroll
        for (int i = 0; i < 4; i++) {
            int v = tid + i * 256;
            int r = v >> 3;
            int c8 = v & 7;
            size_t go = (size_t)r * N_EDGES + c8 * 8;
            cp_async16(aS + r * BKHP + c8 * 8, pa + go);
            cp_async16(bS + r * BKHP + c8 * 8, pb + go);
        }
    };

    auto mma_piece = [&](int tile, int c0, int c1, int& bxo, int& byo) {
        int tt = tile, bx = 0, cnt = 32;
        while (tt >= cnt) { tt -= cnt; bx++; cnt--; }
        const int by = bx + tt;
        bxo = bx; byo = by;
        gA = g_Ta + (size_t)by * 128 * N_EDGES;
        gB = g_Tb + (size_t)bx * 128 * N_EDGES;

#pragma unroll
        for (int mt = 0; mt < 4; mt++)
#pragma unroll
            for (int nt = 0; nt < 4; nt++)
#pragma unroll
                for (int i = 0; i < 4; i++) acc[mt][nt][i] = 0.f;

        if (c0 < c1)     { load_stage(c0, c0 % STAGES); cp_commit(); }
        if (c0 + 1 < c1) { load_stage(c0 + 1, (c0 + 1) % STAGES); cp_commit(); }

        for (int kc = c0; kc < c1; kc++) {
            const int nk = kc + STAGES - 1;
            if (nk < c1) load_stage(nk, nk % STAGES);
            cp_commit();
            cp_wait<STAGES - 2>();
            __syncthreads();

            const uint32_t stageBase = smem32 + (uint32_t)((kc % STAGES) * STAGE_HALVES) * 2;
            const uint32_t aAddr = stageBase + aOff;
            const uint32_t bAddr = stageBase + bOff;

#pragma unroll
            for (int k0 = 0; k0 < BKH; k0 += 16) {
                uint32_t a[4][4];
#pragma unroll
                for (int mt = 0; mt < 4; mt++)
                    ldsm_x4(a[mt][0], a[mt][1], a[mt][2], a[mt][3],
                            aAddr + (uint32_t)(mt * 16 * BKHP + k0) * 2);
                uint32_t b[4][2];
                ldsm_x4(b[0][0], b[0][1], b[1][0], b[1][1],
                        bAddr + (uint32_t)k0 * 2);
                ldsm_x4(b[2][0], b[2][1], b[3][0], b[3][1],
                        bAddr + (uint32_t)(16 * BKHP + k0) * 2);
#pragma unroll
                for (int mt = 0; mt < 4; mt++)
#pragma unroll
                    for (int nt = 0; nt < 4; nt++)
                        mma_fp16(acc[mt][nt][0], acc[mt][nt][1], acc[mt][nt][2], acc[mt][nt][3],
                                 a[mt][0], a[mt][1], a[mt][2], a[mt][3],
                                 b[nt][0], b[nt][1]);
            }
            __syncthreads();
        }
        cp_wait<0>();
        __syncthreads();
    };

    auto epilogue = [&](int by, int bx) {
        float* Cs = reinterpret_cast<float*>(smemc);          // 128 x 129
#pragma unroll
        for (int mt = 0; mt < 4; mt++)
#pragma unroll
            for (int nt = 0; nt < 4; nt++) {
                int r = wm + mt * 16 + grp;
                int c = wn + nt * 8 + qid * 2;
                Cs[r * 129 + c]           = acc[mt][nt][0];
                Cs[r * 129 + c + 1]       = acc[mt][nt][1];
                Cs[(r + 8) * 129 + c]     = acc[mt][nt][2];
                Cs[(r + 8) * 129 + c + 1] = acc[mt][nt][3];
            }
        __syncthreads();
#pragma unroll 4
        for (int step = 0; step < 64; step++) {
            int idx = step * 256 + tid;
            int r = idx >> 7, c = idx & 127;
            size_t gi = (size_t)by * 128 + r;
            size_t gj = (size_t)bx * 128 + c;
            float v = Cs[r * 129 + c];
            float a = adj[gi * N_NODES + gj];
            g_Madj[gi * N_NODES + gj] = __float2half((gi == gj) ? a : v * a);
        }
        if (bx != by) {
#pragma unroll 4
            for (int step = 0; step < 64; step++) {
                int idx = step * 256 + tid;
                int c = idx >> 7, r = idx & 127;   // lanes sweep r -> coalesced
                size_t gi = (size_t)by * 128 + r;
                size_t gj = (size_t)bx * 128 + c;
                float v = Cs[r * 129 + c];
                g_Madj[gj * N_NODES + gi] = __float2half(v * adj[gj * N_NODES + gi]);
            }
        }
        __syncthreads();   // protect Cs before next piece's loads
    };

    long s = range_start(blockIdx.x);
    long e = range_start(blockIdx.x + 1);
    int tailTile = -1, tailC0 = 0, headTile = -1, headC1 = 0;
    if (s & 255) { tailTile = (int)(s >> 8); tailC0 = (int)(s & 255); s = (s + 255) & ~255L; }
    if (e & 255) { headTile = (int)(e >> 8); headC1 = (int)(e & 255); e &= ~255L; }

    int bx, by;

    if (headTile >= 0) {
        mma_piece(headTile, 0, headC1, bx, by);
        float* P = g_Cpart + (size_t)headTile * 16384 + tid;
#pragma unroll
        for (int mt = 0; mt < 4; mt++)
#pragma unroll
            for (int nt = 0; nt < 4; nt++)
#pragma unroll
                for (int i = 0; i < 4; i++)
                    P[(size_t)(mt * 16 + nt * 4 + i) * 256] = acc[mt][nt][i];
        __threadfence();
        __syncthreads();
        if (tid == 0)
            asm volatile("st.global.release.gpu.b32 [%0], %1;"
                         :: "l"(g_flag + headTile), "r"(1) : "memory");
    }

    for (int t = (int)(s >> 8); t < (int)(e >> 8); t++) {
        mma_piece(t, 0, 256, bx, by);
        epilogue(by, bx);
    }

    if (tailTile >= 0) {
        mma_piece(tailTile, tailC0, 256, bx, by);
        if (tid == 0) {
            int v;
            do {
                asm volatile("ld.global.acquire.gpu.b32 %0, [%1];"
                             : "=r"(v) : "l"(g_flag + tailTile) : "memory");
                if (!v) __nanosleep(64);
            } while (!v);
        }
        __syncthreads();
        const float* P = g_Cpart + (size_t)tailTile * 16384 + tid;
#pragma unroll
        for (int mt = 0; mt < 4; mt++)
#pragma unroll
            for (int nt = 0; nt < 4; nt++)
#pragma unroll
                for (int i = 0; i < 4; i++)
                    acc[mt][nt][i] += P[(size_t)(mt * 16 + nt * 4 + i) * 256];
        epilogue(by, bx);
    }
}

// ------------------------------------------------------------------
// GEMM2 fused (fp16 mma + ldmatrix, single pass, K=4096, bias inline):
// BM=64, BN=128, 8 warps (2x4), warp tile 32x32, grid (2, 64).
// ------------------------------------------------------------------
#define H_NKC   (N_NODES / BKH)                 // 64
#define H_A_HALVES (64 * BKHP)                  // 4608
#define H_B_HALVES (128 * BKHP)                 // 9216
#define H_STAGE (H_A_HALVES + H_B_HALVES)       // 13824 halves
#define H_SMEM (STAGES * H_STAGE * 2)           // 82944 B

__global__ __launch_bounds__(256, 2) void gemm2_fused(
    float* __restrict__ out, const float* __restrict__ bias)
{
    extern __shared__ __align__(16) char smemc[];
    __half* smem = reinterpret_cast<__half*>(smemc);
    const int tid = threadIdx.x;
    const int wid = tid >> 5, lane = tid & 31;
    const int grp = lane >> 2, qid = lane & 3;
    const int wm = (wid & 1) * 32;
    const int wn = (wid >> 1) * 32;
    const int m0 = blockIdx.y * 64;
    const int n0 = blockIdx.x * 128;

    const __half* gA = g_Madj + (size_t)m0 * N_NODES;
    const __half* gB = g_HWh + (size_t)n0 * N_NODES;

    const int l7 = lane & 7;
    const int aRow = wm + l7 + 8 * ((lane >> 3) & 1);
    const int aK   = 8 * ((lane >> 4) & 1);
    const int bRow = wn + l7 + 8 * ((lane >> 4) & 1);
    const int bK   = 8 * ((lane >> 3) & 1);
    const uint32_t smem32 = (uint32_t)__cvta_generic_to_shared(smem);
    const uint32_t aOff = (uint32_t)(aRow * BKHP + aK) * 2;
    const uint32_t bOff = (uint32_t)(bRow * BKHP + bK) * 2 + H_A_HALVES * 2;

    float acc[2][4][4];
#pragma unroll
    for (int mt = 0; mt < 2; mt++)
#pragma unroll
        for (int nt = 0; nt < 4; nt++)
#pragma unroll
            for (int i = 0; i < 4; i++) acc[mt][nt][i] = 0.f;

    auto load_stage = [&](int chunk, int buf) {
        __half* aS = smem + buf * H_STAGE;
        __half* bS = aS + H_A_HALVES;
        const __half* pa = gA + (size_t)chunk * BKH;
        const __half* pb = gB + (size_t)chunk * BKH;
#pragma unroll
        for (int i = 0; i < 6; i++) {
            int v = tid + i * 256;              // 0..1535
            int r = v >> 3;                     // 0..191 (A:0-63, B:64-191)
            int c8 = v & 7;
            if (r < 64) {
                cp_async16(aS + r * BKHP + c8 * 8,
                           pa + (size_t)r * N_NODES + c8 * 8);
            } else {
                int rb = r - 64;
                cp_async16(bS + rb * BKHP + c8 * 8,
                           pb + (size_t)rb * N_NODES + c8 * 8);
            }
        }
    };

#pragma unroll
    for (int c = 0; c < STAGES - 1; c++) { load_stage(c, c); cp_commit(); }

    for (int kc = 0; kc < H_NKC; kc++) {
        const int nk = kc + STAGES - 1;
        if (nk < H_NKC) load_stage(nk, nk % STAGES);
        cp_commit();
        cp_wait<STAGES - 2>();
        __syncthreads();

        const uint32_t stageBase = smem32 + (uint32_t)((kc % STAGES) * H_STAGE) * 2;
        const uint32_t aAddr = stageBase + aOff;
        const uint32_t bAddr = stageBase + bOff;

#pragma unroll
        for (int k0 = 0; k0 < BKH; k0 += 16) {
            uint32_t a[2][4];
#pragma unroll
            for (int mt = 0; mt < 2; mt++)
                ldsm_x4(a[mt][0], a[mt][1], a[mt][2], a[mt][3],
                        aAddr + (uint32_t)(mt * 16 * BKHP + k0) * 2);
            uint32_t b[4][2];
#pragma unroll
            for (int np = 0; np < 2; np++)
                ldsm_x4(b[2 * np][0], b[2 * np][1], b[2 * np + 1][0], b[2 * np + 1][1],
                        bAddr + (uint32_t)(np * 16 * BKHP + k0) * 2);
#pragma unroll
            for (int mt = 0; mt < 2; mt++)
#pragma unroll
                for (int nt = 0; nt < 4; nt++)
                    mma_fp16(acc[mt][nt][0], acc[mt][nt][1], acc[mt][nt][2], acc[mt][nt][3],
                             a[mt][0], a[mt][1], a[mt][2], a[mt][3],
                             b[nt][0], b[nt][1]);
        }
        __syncthreads();
    }

#pragma unroll
    for (int mt = 0; mt < 2; mt++)
#pragma unroll
        for (int nt = 0; nt < 4; nt++) {
            int r = m0 + wm + mt * 16 + grp;
            int c = n0 + wn + nt * 8 + qid * 2;
            float b0 = bias[c], b1 = bias[c + 1];
            out[(size_t)r * D_OUT + c]           = acc[mt][nt][0] + b0;
            out[(size_t)r * D_OUT + c + 1]       = acc[mt][nt][1] + b1;
            out[(size_t)(r + 8) * D_OUT + c]     = acc[mt][nt][2] + b0;
            out[(size_t)(r + 8) * D_OUT + c + 1] = acc[mt][nt][3] + b1;
        }
}

// ------------------------------------------------------------------
// Launch: fork sgemm at the very start (independent of everything on
// the null stream); join before gemm2.
// ------------------------------------------------------------------
extern "C" void kernel_launch(void* const* d_in, const int* in_sizes, int n_in,
                              void* d_out, int out_size) {
    const float* H_v  = (const float*)d_in[0];
    const float* ef   = (const float*)d_in[1];
    const float* adj  = (const float*)d_in[2];
    const float* T    = (const float*)d_in[3];
    const float* W    = (const float*)d_in[4];
    const float* bias = (const float*)d_in[5];
    const float* p    = (const float*)d_in[6];
    float* out = (float*)d_out;

    __half* pHWh = nullptr;
    cudaGetSymbolAddress((void**)&pHWh, g_HWh);

    cudaFuncSetAttribute(syrk_sched,
                         cudaFuncAttributeMaxDynamicSharedMemorySize, SYRK_SMEM);
    cudaFuncSetAttribute(gemm2_fused,
                         cudaFuncAttributeMaxDynamicSharedMemorySize, H_SMEM);

    cudaStream_t s2 = nullptr;
    cudaEvent_t eFork = nullptr, eJoin = nullptr;
    bool forked = (cudaStreamCreateWithFlags(&s2, cudaStreamNonBlocking) == cudaSuccess)
               && (cudaEventCreateWithFlags(&eFork, cudaEventDisableTiming) == cudaSuccess)
               && (cudaEventCreateWithFlags(&eJoin, cudaEventDisableTiming) == cudaSuccess);

    if (forked) {
        // fork immediately: sgemm depends only on H_v/W
        cudaEventRecord(eFork, 0);
        cudaStreamWaitEvent(s2, eFork, 0);
        sgemm_kernel<<<dim3(D_OUT / 64, N_NODES / 64), 256, 0, s2>>>(
            H_v, W, pHWh, N_NODES, D_OUT, 256);
        cudaEventRecord(eJoin, s2);
    }

    // 1. per-edge scalar (fp16) + flag reset
    edge_s_kernel<<<N_EDGES / 256, 256>>>(ef, p);

    if (!forked) {
        sgemm_kernel<<<dim3(D_OUT / 64, N_NODES / 64), 256>>>(
            H_v, W, pHWh, N_NODES, D_OUT, 256);
    }

    // 2. Ta = fp16(T), Tb = Ta (x) fp16(s)
    scale2_kernel<<<(int)(((size_t)N_NODES * N_EDGES / 8) / 256), 256>>>(T);
    // 3. Madj: balanced one-wave SYRK with in-kernel combine
    syrk_sched<<<NCTA_A, 256, SYRK_SMEM>>>(adj);

    if (forked) cudaStreamWaitEvent(0, eJoin, 0);   // join before gemm2

    // 4. out = Madj @ HWt^T + bias (single pass, BN=128)
    gemm2_fused<<<dim3(D_OUT / 128, N_NODES / 64), 256, H_SMEM>>>(out, bias);
}